// round 6
// baseline (speedup 1.0000x reference)
#include <cuda_runtime.h>
#include <math.h>
#include <stdint.h>

#define SEQ 4096
#define DIM 1280
#define NHEAD 16
#define HD 80
#define HIDDEN 5120

// ---------------- scratch (device globals; no allocation allowed) ----------
__device__ float g_ln[SEQ * DIM];
__device__ float g_qkv[SEQ * 3 * DIM];
__device__ float g_attn[SEQ * DIM];
__device__ float g_h1[SEQ * DIM];
__device__ float g_fc1[SEQ * HIDDEN];
// rounded weights: qkv | proj | fc1 | fc2
#define W_QKV_OFF  0
#define W_PROJ_OFF 4915200
#define W_FC1_OFF  6553600
#define W_FC2_OFF  13107200
__device__ float g_w[19660800];

__device__ __forceinline__ float rnd_tf32(float x) {
    float r;
    asm("cvt.rna.tf32.f32 %0, %1;" : "=f"(r) : "f"(x));
    return r;
}

// ---------------- weight pre-rounding (once per launch, ~25us total) -------
__global__ void roundw_kernel(const float* __restrict__ s,
                              float* __restrict__ d, int n4) {
    int i = blockIdx.x * 256 + threadIdx.x;
    if (i < n4) {
        float4 v = ((const float4*)s)[i];
        v.x = rnd_tf32(v.x); v.y = rnd_tf32(v.y);
        v.z = rnd_tf32(v.z); v.w = rnd_tf32(v.w);
        ((float4*)d)[i] = v;
    }
}

// ---------------- layernorm (output rounded to tf32 grid) ------------------
__global__ void ln_kernel(const float* __restrict__ x,
                          const float* __restrict__ sc,
                          const float* __restrict__ bi,
                          float* __restrict__ y) {
    int row = blockIdx.x;
    int t = threadIdx.x;
    const float* xr = x + (size_t)row * DIM;
    float s = 0.f, s2 = 0.f;
    #pragma unroll
    for (int i = t; i < DIM; i += 256) {
        float v = xr[i];
        s += v; s2 += v * v;
    }
    #pragma unroll
    for (int o = 16; o; o >>= 1) {
        s  += __shfl_xor_sync(~0u, s,  o);
        s2 += __shfl_xor_sync(~0u, s2, o);
    }
    __shared__ float sh[16];
    int wid = t >> 5, lane = t & 31;
    if (lane == 0) { sh[wid] = s; sh[wid + 8] = s2; }
    __syncthreads();
    float S = 0.f, S2 = 0.f;
    #pragma unroll
    for (int w = 0; w < 8; w++) { S += sh[w]; S2 += sh[w + 8]; }
    float mu = S * (1.f / DIM);
    float var = S2 * (1.f / DIM) - mu * mu;
    float inv = rsqrtf(var + 1e-6f);
    float* yr = y + (size_t)row * DIM;
    #pragma unroll
    for (int i = t; i < DIM; i += 256)
        yr[i] = rnd_tf32((xr[i] - mu) * inv * sc[i] + bi[i]);
}

// ---------------- TF32 tensor-core GEMM, 3-stage cp.async pipeline ---------
// C = A(MxK) * B(KxN) + bias; EPI 0: bias, 1: bias+res, 2: rnd(quickgelu(bias))
#define BM 128
#define BN 128
#define BKT 16
#define ASTR 20    // A row stride: ldmatrix conflict-free
#define BSN 136    // B row stride: 136 mod 32 = 8 -> frag LDS conflict-free
#define NSTAGE 3
#define A_ST (BM * ASTR)      // 2560 floats / stage
#define B_ST (BKT * BSN)      // 2176 floats / stage
#define GSMEM ((NSTAGE * (A_ST + B_ST)) * sizeof(float))  // 56832 B -> 2 CTA/SM

__device__ __forceinline__ uint32_t smem_u32(const void* p) {
    return (uint32_t)__cvta_generic_to_shared(p);
}

__device__ __forceinline__ void cp16(uint32_t dst, const void* src) {
    asm volatile("cp.async.cg.shared.global [%0], [%1], 16;"
                 :: "r"(dst), "l"(src));
}
__device__ __forceinline__ void cp_commit() {
    asm volatile("cp.async.commit_group;");
}
template <int N>
__device__ __forceinline__ void cp_wait() {
    asm volatile("cp.async.wait_group %0;" :: "n"(N));
}

__device__ __forceinline__ void ldsm_x4(uint32_t& r0, uint32_t& r1,
                                        uint32_t& r2, uint32_t& r3,
                                        uint32_t addr) {
    asm volatile("ldmatrix.sync.aligned.m8n8.x4.shared.b16 {%0,%1,%2,%3},[%4];"
                 : "=r"(r0), "=r"(r1), "=r"(r2), "=r"(r3) : "r"(addr));
}

__device__ __forceinline__ void mma_tf32(float c[4],
                                         uint32_t a0, uint32_t a1,
                                         uint32_t a2, uint32_t a3,
                                         uint32_t b0, uint32_t b1) {
    asm volatile(
        "mma.sync.aligned.m16n8k8.row.col.f32.tf32.tf32.f32 "
        "{%0,%1,%2,%3},{%4,%5,%6,%7},{%8,%9},{%0,%1,%2,%3};"
        : "+f"(c[0]), "+f"(c[1]), "+f"(c[2]), "+f"(c[3])
        : "r"(a0), "r"(a1), "r"(a2), "r"(a3), "r"(b0), "r"(b1));
}

template <int EPI>
__global__ void __launch_bounds__(256, 2)
tgemm(const float* __restrict__ A, const float* __restrict__ B,
      const float* __restrict__ bias, const float* __restrict__ res,
      float* __restrict__ C, int M, int N, int K) {
    extern __shared__ float smem[];
    float* As = smem;                       // NSTAGE * A_ST
    float* Bs = smem + NSTAGE * A_ST;       // NSTAGE * B_ST

    int t = threadIdx.x;
    int lane = t & 31, warp = t >> 5;
    int wr = warp >> 2, wc = warp & 3;      // 2x4 warp grid (64x32 warp tiles)
    int m0 = blockIdx.y * BM, n0 = blockIdx.x * BN;
    int sub = lane >> 3, srow = lane & 7;   // ldmatrix addressing
    int g8 = lane >> 2, tig = lane & 3;     // mma fragment coords

    float acc[4][4][4];
    #pragma unroll
    for (int i = 0; i < 4; i++)
        #pragma unroll
        for (int j = 0; j < 4; j++)
            #pragma unroll
            for (int e = 0; e < 4; e++) acc[i][j][e] = 0.f;

    const float* Ag = A + (size_t)m0 * K;
    const float* Bg = B + n0;

    // A tile: 128m x 16k = 512 16B-chunks; ia -> m=ia>>2, kc=ia&3
    // B tile:  16k x 128n = 512 16B-chunks; ib -> k=ib>>5, nc=ib&31
    auto issue = [&](int kt) {
        int buf = kt % NSTAGE;
        int k0 = kt * BKT;
        uint32_t abase = smem_u32(As + buf * A_ST);
        uint32_t bbase = smem_u32(Bs + buf * B_ST);
        #pragma unroll
        for (int r = 0; r < 2; r++) {
            int ia = t + r * 256;
            int m = ia >> 2, kc = ia & 3;
            cp16(abase + (m * ASTR + kc * 4) * 4,
                 Ag + (size_t)m * K + k0 + kc * 4);
            int k = ia >> 5, nc = ia & 31;
            cp16(bbase + (k * BSN + nc * 4) * 4,
                 Bg + (size_t)(k0 + k) * N + nc * 4);
        }
    };

    int nk = K / BKT;
    issue(0); cp_commit();
    issue(1); cp_commit();

    for (int kt = 0; kt < nk; kt++) {
        cp_wait<1>();
        __syncthreads();
        // barrier certifies all warps finished iter kt-1, so overwriting
        // buf (kt+2)%3 == (kt-1)%3 is safe; single barrier per k-tile.
        if (kt + 2 < nk) issue(kt + 2);
        cp_commit();

        int buf = kt % NSTAGE;
        const float* As_ = As + buf * A_ST;
        const float* Bs_ = Bs + buf * B_ST;

        #pragma unroll
        for (int ks = 0; ks < 2; ks++) {
            int k0 = ks * 8;
            uint32_t af[4][4];
            uint32_t bf[4][2];
            #pragma unroll
            for (int i = 0; i < 4; i++) {
                const float* base = &As_[(wr * 64 + i * 16 + (sub & 1) * 8 + srow) * ASTR
                                         + k0 + (sub >> 1) * 4];
                ldsm_x4(af[i][0], af[i][1], af[i][2], af[i][3], smem_u32(base));
            }
            #pragma unroll
            for (int j = 0; j < 4; j++) {
                const float* bp = &Bs_[(k0 + tig) * BSN + wc * 32 + j * 8 + g8];
                bf[j][0] = __float_as_uint(bp[0]);
                bf[j][1] = __float_as_uint(bp[4 * BSN]);
            }
            #pragma unroll
            for (int i = 0; i < 4; i++)
                #pragma unroll
                for (int j = 0; j < 4; j++)
                    mma_tf32(acc[i][j], af[i][0], af[i][1], af[i][2], af[i][3],
                             bf[j][0], bf[j][1]);
        }
    }

    // epilogue: c{0,1} = row g8, cols 2*tig,2*tig+1; c{2,3} = row g8+8
    #pragma unroll
    for (int i = 0; i < 4; i++) {
        int mrow = m0 + wr * 64 + i * 16 + g8;
        #pragma unroll
        for (int j = 0; j < 4; j++) {
            int ncol = n0 + wc * 32 + j * 8 + tig * 2;
            #pragma unroll
            for (int h = 0; h < 2; h++) {
                int mm = mrow + h * 8;
                float2 v;
                v.x = acc[i][j][h * 2 + 0] + bias[ncol];
                v.y = acc[i][j][h * 2 + 1] + bias[ncol + 1];
                if (EPI == 1) {
                    const float2 r2 = *(const float2*)(res + (size_t)mm * N + ncol);
                    v.x += r2.x; v.y += r2.y;
                }
                if (EPI == 2) {
                    // quickgelu, rounded: fc1 output feeds FC2's mma A operand
                    v.x = rnd_tf32(v.x / (1.f + __expf(-1.702f * v.x)));
                    v.y = rnd_tf32(v.y / (1.f + __expf(-1.702f * v.y)));
                }
                *(float2*)(C + (size_t)mm * N + ncol) = v;
            }
        }
    }
}

// ---------------- RoPE on q and k (in place on qkv buffer) -----------------
__global__ void rope_kernel(float* __restrict__ qkv,
                            const float* __restrict__ freqs) {
    int n = blockIdx.x;
    int t = threadIdx.x;
    __shared__ float fc[40], fs[40];
    if (t < 40) {
        float f = freqs[(size_t)n * 40 + t];
        fc[t] = cosf(f);
        fs[t] = sinf(f);
    }
    __syncthreads();
    for (int i = t; i < 1280; i += 256) {
        int j = i / 640;
        int rem = i - j * 640;
        int h = rem / 40;
        int d = rem - h * 40;
        float* base = qkv + (size_t)n * (3 * DIM) + j * DIM + h * HD;
        float x1 = base[d];
        float x2 = base[d + 40];
        int plo = d >> 1;
        int phi = 20 + (d >> 1);
        base[d]      = x1 * fc[plo] - x2 * fs[plo];
        base[d + 40] = x2 * fc[phi] + x1 * fs[phi];
    }
}

// ---------------- flash attention (block-diagonal via cu_seqlens) ----------
#define BQ 64
#define BK 64
#define QSTR 84
#define SSTR 68

__global__ void __launch_bounds__(256)
flash_kernel(const float* __restrict__ qkv, const int* __restrict__ cu,
             float* __restrict__ out) {
    extern __shared__ float sm[];
    float* Qs = sm;
    float* Ks = Qs + BQ * QSTR;
    float* Vs = Ks + BK * QSTR;
    float* Ss = Vs + BK * QSTR;
    __shared__ int sstart[BQ], send[BQ], sbound[2];

    int q0 = blockIdx.x * BQ;
    int h = blockIdx.y;
    int t = threadIdx.x;

    for (int i = t; i < BQ * HD; i += 256) {
        int r = i / HD, d = i - r * HD;
        Qs[r * QSTR + d] = qkv[(size_t)(q0 + r) * (3 * DIM) + h * HD + d];
    }
    if (t < BQ) {
        int row = q0 + t;
        int s = 0, e = SEQ;
        #pragma unroll
        for (int i = 0; i < 4; i++)
            if (row >= cu[i] && row < cu[i + 1]) { s = cu[i]; e = cu[i + 1]; }
        sstart[t] = s; send[t] = e;
    }
    __syncthreads();
    if (t == 0) {
        int mn = sstart[0], mx = send[0];
        for (int i = 1; i < BQ; i++) {
            mn = min(mn, sstart[i]);
            mx = max(mx, send[i]);
        }
        sbound[0] = mn; sbound[1] = mx;
    }
    __syncthreads();
    int kmin = sbound[0], kmax = sbound[1];

    int qi = t >> 2;
    int dg = t & 3;
    int mystart = sstart[qi], myend = send[qi];

    float acc[20];
    #pragma unroll
    for (int j = 0; j < 20; j++) acc[j] = 0.f;
    float m = -1e30f, l = 0.f;
    const float scale = 0.1118033988749895f;

    for (int kb = kmin; kb < kmax; kb += BK) {
        for (int i = t; i < BK * HD; i += 256) {
            int r = i / HD, d = i - r * HD;
            size_t base = (size_t)(kb + r) * (3 * DIM) + h * HD + d;
            Ks[r * QSTR + d] = qkv[base + DIM];
            Vs[r * QSTR + d] = qkv[base + 2 * DIM];
        }
        __syncthreads();

        float svals[16];
        float tmax = -1e30f;
        const float4* q4 = (const float4*)(Qs + qi * QSTR);
        #pragma unroll 4
        for (int kk = 0; kk < 16; kk++) {
            int k = kk * 4 + dg;
            const float4* k4 = (const float4*)(Ks + k * QSTR);
            float s = 0.f;
            #pragma unroll
            for (int d4 = 0; d4 < 20; d4++) {
                float4 qa = q4[d4];
                float4 ka = k4[d4];
                s += qa.x * ka.x + qa.y * ka.y + qa.z * ka.z + qa.w * ka.w;
            }
            int kg = kb + k;
            s = (kg >= mystart && kg < myend) ? s * scale : -1e30f;
            svals[kk] = s;
            tmax = fmaxf(tmax, s);
        }
        tmax = fmaxf(tmax, __shfl_xor_sync(~0u, tmax, 1));
        tmax = fmaxf(tmax, __shfl_xor_sync(~0u, tmax, 2));
        float newm = fmaxf(fmaxf(m, tmax), -1e28f);

        float psum = 0.f;
        #pragma unroll
        for (int kk = 0; kk < 16; kk++) {
            float p = __expf(svals[kk] - newm);
            psum += p;
            Ss[qi * SSTR + kk * 4 + dg] = p;
        }
        psum += __shfl_xor_sync(~0u, psum, 1);
        psum += __shfl_xor_sync(~0u, psum, 2);
        __syncwarp();

        float corr = __expf(m - newm);
        #pragma unroll
        for (int j = 0; j < 20; j++) acc[j] *= corr;
        for (int k = 0; k < BK; k++) {
            float p = Ss[qi * SSTR + k];
            const float4* v4 = (const float4*)(Vs + k * QSTR + dg * 20);
            #pragma unroll
            for (int jj = 0; jj < 5; jj++) {
                float4 vv = v4[jj];
                acc[jj * 4 + 0] += p * vv.x;
                acc[jj * 4 + 1] += p * vv.y;
                acc[jj * 4 + 2] += p * vv.z;
                acc[jj * 4 + 3] += p * vv.w;
            }
        }
        l = l * corr + psum;
        m = newm;
        __syncthreads();
    }

    // output rounded: attn feeds proj's mma A operand
    float invl = 1.f / l;
    float* orow = out + (size_t)(q0 + qi) * DIM + h * HD + dg * 20;
    #pragma unroll
    for (int j = 0; j < 20; j++) orow[j] = rnd_tf32(acc[j] * invl);
}

// ---------------- launch ---------------------------------------------------
extern "C" void kernel_launch(void* const* d_in, const int* in_sizes, int n_in,
                              void* d_out, int out_size) {
    const float* hidden = (const float*)d_in[0];
    const float* rot    = (const float*)d_in[1];
    const int*   cu     = (const int*)d_in[2];
    const float* w_qkv  = (const float*)d_in[3];
    const float* b_qkv  = (const float*)d_in[4];
    const float* w_proj = (const float*)d_in[5];
    const float* b_proj = (const float*)d_in[6];
    const float* w_fc1  = (const float*)d_in[7];
    const float* b_fc1  = (const float*)d_in[8];
    const float* w_fc2  = (const float*)d_in[9];
    const float* b_fc2  = (const float*)d_in[10];
    const float* ln1s   = (const float*)d_in[11];
    const float* ln1b   = (const float*)d_in[12];
    const float* ln2s   = (const float*)d_in[13];
    const float* ln2b   = (const float*)d_in[14];
    float* out = (float*)d_out;

    float *ln, *qkvb, *attn, *h1, *fc1, *w;
    cudaGetSymbolAddress((void**)&ln, g_ln);
    cudaGetSymbolAddress((void**)&qkvb, g_qkv);
    cudaGetSymbolAddress((void**)&attn, g_attn);
    cudaGetSymbolAddress((void**)&h1, g_h1);
    cudaGetSymbolAddress((void**)&fc1, g_fc1);
    cudaGetSymbolAddress((void**)&w, g_w);

    const int FLASH_SMEM = (3 * BQ * QSTR + BQ * SSTR) * sizeof(float);
    cudaFuncSetAttribute(flash_kernel,
                         cudaFuncAttributeMaxDynamicSharedMemorySize,
                         FLASH_SMEM);
    cudaFuncSetAttribute(tgemm<0>,
                         cudaFuncAttributeMaxDynamicSharedMemorySize, GSMEM);
    cudaFuncSetAttribute(tgemm<1>,
                         cudaFuncAttributeMaxDynamicSharedMemorySize, GSMEM);
    cudaFuncSetAttribute(tgemm<2>,
                         cudaFuncAttributeMaxDynamicSharedMemorySize, GSMEM);

    // 0. round weights to tf32 grid (so in-loop truncation == rna rounding)
    roundw_kernel<<<(4915200 / 4 + 255) / 256, 256>>>(w_qkv,  w + W_QKV_OFF,  4915200 / 4);
    roundw_kernel<<<(1638400 / 4 + 255) / 256, 256>>>(w_proj, w + W_PROJ_OFF, 1638400 / 4);
    roundw_kernel<<<(6553600 / 4 + 255) / 256, 256>>>(w_fc1,  w + W_FC1_OFF,  6553600 / 4);
    roundw_kernel<<<(6553600 / 4 + 255) / 256, 256>>>(w_fc2,  w + W_FC2_OFF,  6553600 / 4);

    // 1. LN1 (output tf32-rounded)
    ln_kernel<<<SEQ, 256>>>(hidden, ln1s, ln1b, ln);
    // 2. QKV GEMM (+bias)
    tgemm<0><<<dim3((3 * DIM) / BN, SEQ / BM), 256, GSMEM>>>(
        ln, w + W_QKV_OFF, b_qkv, nullptr, qkvb, SEQ, 3 * DIM, DIM);
    // 3. RoPE on q,k
    rope_kernel<<<SEQ, 256>>>(qkvb, rot);
    // 4. attention (output tf32-rounded)
    flash_kernel<<<dim3(SEQ / BQ, NHEAD), 256, FLASH_SMEM>>>(qkvb, cu, attn);
    // 5. proj GEMM + bias + residual(hidden) -> h1
    tgemm<1><<<dim3(DIM / BN, SEQ / BM), 256, GSMEM>>>(
        attn, w + W_PROJ_OFF, b_proj, hidden, h1, SEQ, DIM, DIM);
    // 6. LN2 (output tf32-rounded)
    ln_kernel<<<SEQ, 256>>>(h1, ln2s, ln2b, ln);
    // 7. FC1 + bias + quickgelu (output tf32-rounded)
    tgemm<2><<<dim3(HIDDEN / BN, SEQ / BM), 256, GSMEM>>>(
        ln, w + W_FC1_OFF, b_fc1, nullptr, fc1, SEQ, HIDDEN, DIM);
    // 8. FC2 + bias + residual(h1) -> out
    tgemm<1><<<dim3(DIM / BN, SEQ / BM), 256, GSMEM>>>(
        fc1, w + W_FC2_OFF, b_fc2, h1, out, SEQ, DIM, HIDDEN);
}

// round 9
// speedup vs baseline: 1.2657x; 1.2657x over previous
#include <cuda_runtime.h>
#include <cuda_fp16.h>
#include <math.h>
#include <stdint.h>

#define SEQ 4096
#define DIM 1280
#define NHEAD 16
#define HD 80
#define HIDDEN 5120

// ---------------- scratch (device globals; no allocation allowed) ----------
__device__ __half g_lnh[SEQ * DIM];
__device__ float  g_qkv[SEQ * 3 * DIM];
__device__ __half g_attnh[SEQ * DIM];
__device__ float  g_h1[SEQ * DIM];
__device__ __half g_fc1h[SEQ * HIDDEN];
// transposed fp16 weights [N][K]: qkv | proj | fc1 | fc2
#define W_QKV_OFF  0
#define W_PROJ_OFF 4915200
#define W_FC1_OFF  6553600
#define W_FC2_OFF  13107200
__device__ __half g_wh[19660800];

__device__ __forceinline__ uint32_t smem_u32(const void* p) {
    return (uint32_t)__cvta_generic_to_shared(p);
}

// ---------------- weight transpose + fp16 convert (once per launch) --------
// in: w [K][N] row-major fp32; out: wT [N][K] row-major fp16
__global__ void twk(const float* __restrict__ s, __half* __restrict__ d,
                    int K, int N) {
    __shared__ float tile[32][33];
    int c0 = blockIdx.x * 32, r0 = blockIdx.y * 32;
    int tx = threadIdx.x, ty = threadIdx.y;
    #pragma unroll
    for (int i = 0; i < 4; i++)
        tile[ty + 8 * i][tx] = s[(size_t)(r0 + ty + 8 * i) * N + c0 + tx];
    __syncthreads();
    #pragma unroll
    for (int i = 0; i < 4; i++)
        d[(size_t)(c0 + ty + 8 * i) * K + r0 + tx] =
            __float2half_rn(tile[tx][ty + 8 * i]);
}

// ---------------- layernorm (fp32 in, fp16 out) ----------------------------
__global__ void ln_kernel(const float* __restrict__ x,
                          const float* __restrict__ sc,
                          const float* __restrict__ bi,
                          __half* __restrict__ y) {
    int row = blockIdx.x;
    int t = threadIdx.x;
    const float* xr = x + (size_t)row * DIM;
    float s = 0.f, s2 = 0.f;
    #pragma unroll
    for (int i = t; i < DIM; i += 256) {
        float v = xr[i];
        s += v; s2 += v * v;
    }
    #pragma unroll
    for (int o = 16; o; o >>= 1) {
        s  += __shfl_xor_sync(~0u, s,  o);
        s2 += __shfl_xor_sync(~0u, s2, o);
    }
    __shared__ float sh[16];
    int wid = t >> 5, lane = t & 31;
    if (lane == 0) { sh[wid] = s; sh[wid + 8] = s2; }
    __syncthreads();
    float S = 0.f, S2 = 0.f;
    #pragma unroll
    for (int w = 0; w < 8; w++) { S += sh[w]; S2 += sh[w + 8]; }
    float mu = S * (1.f / DIM);
    float var = S2 * (1.f / DIM) - mu * mu;
    float inv = rsqrtf(var + 1e-6f);
    __half* yr = y + (size_t)row * DIM;
    #pragma unroll
    for (int i = t; i < DIM; i += 256)
        yr[i] = __float2half_rn((xr[i] - mu) * inv * sc[i] + bi[i]);
}

// ---------------- FP16 tensor-core GEMM, 3-stage cp.async pipeline ---------
// C = A(MxK,fp16) * Bt(NxK,fp16)^T + bias
// EPI 0: fp32 C + bias; 1: fp32 C + bias + res; 2: fp16 C = gelu(bias)
#define BM 128
#define BN 128
#define BKH 32      // k per tile, halves
#define ASTRH 40    // row stride (halves) = 80B: banks r*20 mod 32 distinct
#define NSTAGE 3
#define A_STH (BM * ASTRH)     // 5120 halves / stage
#define B_STH (BN * ASTRH)     // 5120 halves / stage
#define GSMEM ((NSTAGE * (A_STH + B_STH)) * sizeof(__half))  // 61440 B

__device__ __forceinline__ void cp16(uint32_t dst, const void* src) {
    asm volatile("cp.async.cg.shared.global [%0], [%1], 16;"
                 :: "r"(dst), "l"(src));
}
__device__ __forceinline__ void cp_commit() {
    asm volatile("cp.async.commit_group;");
}
template <int N>
__device__ __forceinline__ void cp_wait() {
    asm volatile("cp.async.wait_group %0;" :: "n"(N));
}

__device__ __forceinline__ void ldsm_x4(uint32_t& r0, uint32_t& r1,
                                        uint32_t& r2, uint32_t& r3,
                                        uint32_t addr) {
    asm volatile("ldmatrix.sync.aligned.m8n8.x4.shared.b16 {%0,%1,%2,%3},[%4];"
                 : "=r"(r0), "=r"(r1), "=r"(r2), "=r"(r3) : "r"(addr));
}
__device__ __forceinline__ void ldsm_x2(uint32_t& r0, uint32_t& r1,
                                        uint32_t addr) {
    asm volatile("ldmatrix.sync.aligned.m8n8.x2.shared.b16 {%0,%1},[%2];"
                 : "=r"(r0), "=r"(r1) : "r"(addr));
}

__device__ __forceinline__ void mma_f16(float c[4],
                                        uint32_t a0, uint32_t a1,
                                        uint32_t a2, uint32_t a3,
                                        uint32_t b0, uint32_t b1) {
    asm volatile(
        "mma.sync.aligned.m16n8k16.row.col.f32.f16.f16.f32 "
        "{%0,%1,%2,%3},{%4,%5,%6,%7},{%8,%9},{%0,%1,%2,%3};"
        : "+f"(c[0]), "+f"(c[1]), "+f"(c[2]), "+f"(c[3])
        : "r"(a0), "r"(a1), "r"(a2), "r"(a3), "r"(b0), "r"(b1));
}

template <int EPI>
__global__ void __launch_bounds__(256, 2)
hgemm(const __half* __restrict__ A, const __half* __restrict__ Bt,
      const float* __restrict__ bias, const float* __restrict__ res,
      void* __restrict__ Cv, int M, int N, int K) {
    extern __shared__ __half smem[];
    __half* As = smem;                       // NSTAGE * A_STH
    __half* Bs = smem + NSTAGE * A_STH;      // NSTAGE * B_STH

    int t = threadIdx.x;
    int lane = t & 31, warp = t >> 5;
    int wr = warp >> 2, wc = warp & 3;       // 2x4 warp grid (64x32 tiles)
    int m0 = blockIdx.y * BM, n0 = blockIdx.x * BN;
    int r16 = lane & 15, s16 = lane >> 4;    // A ldmatrix addressing
    int r8 = lane & 7,  s8 = (lane >> 3) & 1; // B ldmatrix addressing
    int g8 = lane >> 2, tig = lane & 3;      // mma fragment coords

    float acc[4][4][4];
    #pragma unroll
    for (int i = 0; i < 4; i++)
        #pragma unroll
        for (int j = 0; j < 4; j++)
            #pragma unroll
            for (int e = 0; e < 4; e++) acc[i][j][e] = 0.f;

    const __half* Ag = A + (size_t)m0 * K;
    const __half* Bg = Bt + (size_t)n0 * K;

    // A tile: 128 rows x 32 halves = 4 16B-chunks/row = 512 chunks (2/thread)
    // B tile: 128 rows x 32 halves likewise
    auto issue = [&](int kt) {
        int buf = kt % NSTAGE;
        int k0 = kt * BKH;
        uint32_t ab = smem_u32(As + buf * A_STH);
        uint32_t bb = smem_u32(Bs + buf * B_STH);
        #pragma unroll
        for (int r = 0; r < 2; r++) {
            int ia = t + r * 256;
            int row = ia >> 2, c = ia & 3;
            cp16(ab + (row * ASTRH + c * 8) * 2,
                 Ag + (size_t)row * K + k0 + c * 8);
            cp16(bb + (row * ASTRH + c * 8) * 2,
                 Bg + (size_t)row * K + k0 + c * 8);
        }
    };

    int nk = K / BKH;
    issue(0); cp_commit();
    issue(1); cp_commit();

    for (int kt = 0; kt < nk; kt++) {
        cp_wait<1>();
        __syncthreads();
        // barrier certifies all warps finished iter kt-1 -> safe to overwrite
        if (kt + 2 < nk) issue(kt + 2);
        cp_commit();

        int buf = kt % NSTAGE;
        const __half* As_ = As + buf * A_STH;
        const __half* Bs_ = Bs + buf * B_STH;

        #pragma unroll
        for (int ks = 0; ks < 2; ks++) {
            int k0 = ks * 16;
            uint32_t af[4][4], bf[4][2];
            #pragma unroll
            for (int i = 0; i < 4; i++) {
                const __half* p = &As_[(wr * 64 + i * 16 + r16) * ASTRH
                                       + k0 + s16 * 8];
                ldsm_x4(af[i][0], af[i][1], af[i][2], af[i][3], smem_u32(p));
            }
            #pragma unroll
            for (int j = 0; j < 4; j++) {
                const __half* p = &Bs_[(wc * 32 + j * 8 + r8) * ASTRH
                                       + k0 + s8 * 8];
                ldsm_x2(bf[j][0], bf[j][1], smem_u32(p));
            }
            #pragma unroll
            for (int i = 0; i < 4; i++)
                #pragma unroll
                for (int j = 0; j < 4; j++)
                    mma_f16(acc[i][j], af[i][0], af[i][1], af[i][2], af[i][3],
                            bf[j][0], bf[j][1]);
        }
    }

    // epilogue: c{0,1} = row g8, cols 2*tig,2*tig+1; c{2,3} = row g8+8
    #pragma unroll
    for (int i = 0; i < 4; i++) {
        int mrow = m0 + wr * 64 + i * 16 + g8;
        #pragma unroll
        for (int j = 0; j < 4; j++) {
            int ncol = n0 + wc * 32 + j * 8 + tig * 2;
            #pragma unroll
            for (int h = 0; h < 2; h++) {
                int mm = mrow + h * 8;
                float vx = acc[i][j][h * 2 + 0] + bias[ncol];
                float vy = acc[i][j][h * 2 + 1] + bias[ncol + 1];
                if (EPI == 1) {
                    const float2 r2 = *(const float2*)(res + (size_t)mm * N + ncol);
                    vx += r2.x; vy += r2.y;
                }
                if (EPI == 2) {
                    vx = vx / (1.f + __expf(-1.702f * vx));
                    vy = vy / (1.f + __expf(-1.702f * vy));
                    __half2 hv = __floats2half2_rn(vx, vy);
                    *(__half2*)((__half*)Cv + (size_t)mm * N + ncol) = hv;
                } else {
                    float2 v; v.x = vx; v.y = vy;
                    *(float2*)((float*)Cv + (size_t)mm * N + ncol) = v;
                }
            }
        }
    }
}

// ---------------- RoPE on q and k (in place on qkv buffer) -----------------
__global__ void rope_kernel(float* __restrict__ qkv,
                            const float* __restrict__ freqs) {
    int n = blockIdx.x;
    int t = threadIdx.x;
    __shared__ float fc[40], fs[40];
    if (t < 40) {
        float f = freqs[(size_t)n * 40 + t];
        fc[t] = cosf(f);
        fs[t] = sinf(f);
    }
    __syncthreads();
    for (int i = t; i < 1280; i += 256) {
        int j = i / 640;
        int rem = i - j * 640;
        int h = rem / 40;
        int d = rem - h * 40;
        float* base = qkv + (size_t)n * (3 * DIM) + j * DIM + h * HD;
        float x1 = base[d];
        float x2 = base[d + 40];
        int plo = d >> 1;
        int phi = 20 + (d >> 1);
        base[d]      = x1 * fc[plo] - x2 * fs[plo];
        base[d + 40] = x2 * fc[phi] + x1 * fs[phi];
    }
}

// ---------------- flash attention (block-diagonal via cu_seqlens) ----------
#define BQ 64
#define BK 64
#define QSTR 84
#define SSTR 68

__global__ void __launch_bounds__(256)
flash_kernel(const float* __restrict__ qkv, const int* __restrict__ cu,
             __half* __restrict__ out) {
    extern __shared__ float sm[];
    float* Qs = sm;
    float* Ks = Qs + BQ * QSTR;
    float* Vs = Ks + BK * QSTR;
    float* Ss = Vs + BK * QSTR;
    __shared__ int sstart[BQ], send[BQ], sbound[2];

    int q0 = blockIdx.x * BQ;
    int h = blockIdx.y;
    int t = threadIdx.x;

    for (int i = t; i < BQ * HD; i += 256) {
        int r = i / HD, d = i - r * HD;
        Qs[r * QSTR + d] = qkv[(size_t)(q0 + r) * (3 * DIM) + h * HD + d];
    }
    if (t < BQ) {
        int row = q0 + t;
        int s = 0, e = SEQ;
        #pragma unroll
        for (int i = 0; i < 4; i++)
            if (row >= cu[i] && row < cu[i + 1]) { s = cu[i]; e = cu[i + 1]; }
        sstart[t] = s; send[t] = e;
    }
    __syncthreads();
    if (t == 0) {
        int mn = sstart[0], mx = send[0];
        for (int i = 1; i < BQ; i++) {
            mn = min(mn, sstart[i]);
            mx = max(mx, send[i]);
        }
        sbound[0] = mn; sbound[1] = mx;
    }
    __syncthreads();
    int kmin = sbound[0], kmax = sbound[1];

    int qi = t >> 2;
    int dg = t & 3;
    int mystart = sstart[qi], myend = send[qi];

    float acc[20];
    #pragma unroll
    for (int j = 0; j < 20; j++) acc[j] = 0.f;
    float m = -1e30f, l = 0.f;
    const float scale = 0.1118033988749895f;

    for (int kb = kmin; kb < kmax; kb += BK) {
        for (int i = t; i < BK * HD; i += 256) {
            int r = i / HD, d = i - r * HD;
            size_t base = (size_t)(kb + r) * (3 * DIM) + h * HD + d;
            Ks[r * QSTR + d] = qkv[base + DIM];
            Vs[r * QSTR + d] = qkv[base + 2 * DIM];
        }
        __syncthreads();

        float svals[16];
        float tmax = -1e30f;
        const float4* q4 = (const float4*)(Qs + qi * QSTR);
        #pragma unroll 4
        for (int kk = 0; kk < 16; kk++) {
            int k = kk * 4 + dg;
            const float4* k4 = (const float4*)(Ks + k * QSTR);
            float s = 0.f;
            #pragma unroll
            for (int d4 = 0; d4 < 20; d4++) {
                float4 qa = q4[d4];
                float4 ka = k4[d4];
                s += qa.x * ka.x + qa.y * ka.y + qa.z * ka.z + qa.w * ka.w;
            }
            int kg = kb + k;
            s = (kg >= mystart && kg < myend) ? s * scale : -1e30f;
            svals[kk] = s;
            tmax = fmaxf(tmax, s);
        }
        tmax = fmaxf(tmax, __shfl_xor_sync(~0u, tmax, 1));
        tmax = fmaxf(tmax, __shfl_xor_sync(~0u, tmax, 2));
        float newm = fmaxf(fmaxf(m, tmax), -1e28f);

        float psum = 0.f;
        #pragma unroll
        for (int kk = 0; kk < 16; kk++) {
            float p = __expf(svals[kk] - newm);
            psum += p;
            Ss[qi * SSTR + kk * 4 + dg] = p;
        }
        psum += __shfl_xor_sync(~0u, psum, 1);
        psum += __shfl_xor_sync(~0u, psum, 2);
        __syncwarp();

        float corr = __expf(m - newm);
        #pragma unroll
        for (int j = 0; j < 20; j++) acc[j] *= corr;
        for (int k = 0; k < BK; k++) {
            float p = Ss[qi * SSTR + k];
            const float4* v4 = (const float4*)(Vs + k * QSTR + dg * 20);
            #pragma unroll
            for (int jj = 0; jj < 5; jj++) {
                float4 vv = v4[jj];
                acc[jj * 4 + 0] += p * vv.x;
                acc[jj * 4 + 1] += p * vv.y;
                acc[jj * 4 + 2] += p * vv.z;
                acc[jj * 4 + 3] += p * vv.w;
            }
        }
        l = l * corr + psum;
        m = newm;
        __syncthreads();
    }

    // fp16 output: attn feeds proj GEMM's fp16 A operand
    float invl = 1.f / l;
    __half* orow = out + (size_t)(q0 + qi) * DIM + h * HD + dg * 20;
    #pragma unroll
    for (int j = 0; j < 20; j++) orow[j] = __float2half_rn(acc[j] * invl);
}

// ---------------- launch ---------------------------------------------------
extern "C" void kernel_launch(void* const* d_in, const int* in_sizes, int n_in,
                              void* d_out, int out_size) {
    const float* hidden = (const float*)d_in[0];
    const float* rot    = (const float*)d_in[1];
    const int*   cu     = (const int*)d_in[2];
    const float* w_qkv  = (const float*)d_in[3];
    const float* b_qkv  = (const float*)d_in[4];
    const float* w_proj = (const float*)d_in[5];
    const float* b_proj = (const float*)d_in[6];
    const float* w_fc1  = (const float*)d_in[7];
    const float* b_fc1  = (const float*)d_in[8];
    const float* w_fc2  = (const float*)d_in[9];
    const float* b_fc2  = (const float*)d_in[10];
    const float* ln1s   = (const float*)d_in[11];
    const float* ln1b   = (const float*)d_in[12];
    const float* ln2s   = (const float*)d_in[13];
    const float* ln2b   = (const float*)d_in[14];
    float* out = (float*)d_out;

    __half *lnh, *attnh, *fc1h, *wh;
    float *qkvb, *h1;
    cudaGetSymbolAddress((void**)&lnh, g_lnh);
    cudaGetSymbolAddress((void**)&qkvb, g_qkv);
    cudaGetSymbolAddress((void**)&attnh, g_attnh);
    cudaGetSymbolAddress((void**)&h1, g_h1);
    cudaGetSymbolAddress((void**)&fc1h, g_fc1h);
    cudaGetSymbolAddress((void**)&wh, g_wh);

    const int FLASH_SMEM = (3 * BQ * QSTR + BQ * SSTR) * sizeof(float);
    cudaFuncSetAttribute(flash_kernel,
                         cudaFuncAttributeMaxDynamicSharedMemorySize,
                         FLASH_SMEM);
    cudaFuncSetAttribute(hgemm<0>,
                         cudaFuncAttributeMaxDynamicSharedMemorySize, GSMEM);
    cudaFuncSetAttribute(hgemm<1>,
                         cudaFuncAttributeMaxDynamicSharedMemorySize, GSMEM);
    cudaFuncSetAttribute(hgemm<2>,
                         cudaFuncAttributeMaxDynamicSharedMemorySize, GSMEM);

    // 0. transpose + fp16-convert weights -> [N][K]
    twk<<<dim3(3840 / 32, 1280 / 32), dim3(32, 8)>>>(w_qkv,  wh + W_QKV_OFF,  1280, 3840);
    twk<<<dim3(1280 / 32, 1280 / 32), dim3(32, 8)>>>(w_proj, wh + W_PROJ_OFF, 1280, 1280);
    twk<<<dim3(5120 / 32, 1280 / 32), dim3(32, 8)>>>(w_fc1,  wh + W_FC1_OFF,  1280, 5120);
    twk<<<dim3(1280 / 32, 5120 / 32), dim3(32, 8)>>>(w_fc2,  wh + W_FC2_OFF,  5120, 1280);

    // 1. LN1 -> fp16
    ln_kernel<<<SEQ, 256>>>(hidden, ln1s, ln1b, lnh);
    // 2. QKV GEMM (+bias) -> fp32
    hgemm<0><<<dim3((3 * DIM) / BN, SEQ / BM), 256, GSMEM>>>(
        lnh, wh + W_QKV_OFF, b_qkv, nullptr, qkvb, SEQ, 3 * DIM, DIM);
    // 3. RoPE on q,k
    rope_kernel<<<SEQ, 256>>>(qkvb, rot);
    // 4. attention -> fp16
    flash_kernel<<<dim3(SEQ / BQ, NHEAD), 256, FLASH_SMEM>>>(qkvb, cu, attnh);
    // 5. proj GEMM + bias + residual(hidden) -> h1 fp32
    hgemm<1><<<dim3(DIM / BN, SEQ / BM), 256, GSMEM>>>(
        attnh, wh + W_PROJ_OFF, b_proj, hidden, h1, SEQ, DIM, DIM);
    // 6. LN2 -> fp16
    ln_kernel<<<SEQ, 256>>>(h1, ln2s, ln2b, lnh);
    // 7. FC1 + bias + quickgelu -> fp16
    hgemm<2><<<dim3(HIDDEN / BN, SEQ / BM), 256, GSMEM>>>(
        lnh, wh + W_FC1_OFF, b_fc1, nullptr, fc1h, SEQ, HIDDEN, DIM);
    // 8. FC2 + bias + residual(h1) -> out fp32
    hgemm<1><<<dim3(DIM / BN, SEQ / BM), 256, GSMEM>>>(
        fc1h, wh + W_FC2_OFF, b_fc2, h1, out, SEQ, DIM, HIDDEN);
}

// round 11
// speedup vs baseline: 2.8296x; 2.2356x over previous
#include <cuda_runtime.h>
#include <cuda_fp16.h>
#include <math.h>
#include <stdint.h>

#define SEQ 4096
#define DIM 1280
#define NHEAD 16
#define HD 80
#define HIDDEN 5120

// ---------------- scratch (device globals; no allocation allowed) ----------
__device__ __half g_lnh[SEQ * DIM];
__device__ float  g_qkv[SEQ * 3 * DIM];
__device__ __half g_attnh[SEQ * DIM];
__device__ float  g_h1[SEQ * DIM];
__device__ __half g_fc1h[SEQ * HIDDEN];
// transposed fp16 weights [N][K]: qkv | proj | fc1 | fc2
#define W_QKV_OFF  0
#define W_PROJ_OFF 4915200
#define W_FC1_OFF  6553600
#define W_FC2_OFF  13107200
__device__ __half g_wh[19660800];

__device__ __forceinline__ uint32_t smem_u32(const void* p) {
    return (uint32_t)__cvta_generic_to_shared(p);
}

__device__ __forceinline__ uint32_t h2_u32(__half2 v) {
    uint32_t u;
    memcpy(&u, &v, 4);
    return u;
}

// ---------------- weight transpose + fp16 convert (once per launch) --------
__global__ void twk(const float* __restrict__ s, __half* __restrict__ d,
                    int K, int N) {
    __shared__ float tile[32][33];
    int c0 = blockIdx.x * 32, r0 = blockIdx.y * 32;
    int tx = threadIdx.x, ty = threadIdx.y;
    #pragma unroll
    for (int i = 0; i < 4; i++)
        tile[ty + 8 * i][tx] = s[(size_t)(r0 + ty + 8 * i) * N + c0 + tx];
    __syncthreads();
    #pragma unroll
    for (int i = 0; i < 4; i++)
        d[(size_t)(c0 + ty + 8 * i) * K + r0 + tx] =
            __float2half_rn(tile[tx][ty + 8 * i]);
}

// ---------------- layernorm (fp32 in, fp16 out) ----------------------------
__global__ void ln_kernel(const float* __restrict__ x,
                          const float* __restrict__ sc,
                          const float* __restrict__ bi,
                          __half* __restrict__ y) {
    int row = blockIdx.x;
    int t = threadIdx.x;
    const float* xr = x + (size_t)row * DIM;
    float s = 0.f, s2 = 0.f;
    #pragma unroll
    for (int i = t; i < DIM; i += 256) {
        float v = xr[i];
        s += v; s2 += v * v;
    }
    #pragma unroll
    for (int o = 16; o; o >>= 1) {
        s  += __shfl_xor_sync(~0u, s,  o);
        s2 += __shfl_xor_sync(~0u, s2, o);
    }
    __shared__ float sh[16];
    int wid = t >> 5, lane = t & 31;
    if (lane == 0) { sh[wid] = s; sh[wid + 8] = s2; }
    __syncthreads();
    float S = 0.f, S2 = 0.f;
    #pragma unroll
    for (int w = 0; w < 8; w++) { S += sh[w]; S2 += sh[w + 8]; }
    float mu = S * (1.f / DIM);
    float var = S2 * (1.f / DIM) - mu * mu;
    float inv = rsqrtf(var + 1e-6f);
    __half* yr = y + (size_t)row * DIM;
    #pragma unroll
    for (int i = t; i < DIM; i += 256)
        yr[i] = __float2half_rn((xr[i] - mu) * inv * sc[i] + bi[i]);
}

// ---------------- shared mma helpers ---------------------------------------
__device__ __forceinline__ void ldsm_x4(uint32_t& r0, uint32_t& r1,
                                        uint32_t& r2, uint32_t& r3,
                                        uint32_t addr) {
    asm volatile("ldmatrix.sync.aligned.m8n8.x4.shared.b16 {%0,%1,%2,%3},[%4];"
                 : "=r"(r0), "=r"(r1), "=r"(r2), "=r"(r3) : "r"(addr));
}
__device__ __forceinline__ void ldsm_x2(uint32_t& r0, uint32_t& r1,
                                        uint32_t addr) {
    asm volatile("ldmatrix.sync.aligned.m8n8.x2.shared.b16 {%0,%1},[%2];"
                 : "=r"(r0), "=r"(r1) : "r"(addr));
}
__device__ __forceinline__ void mma_f16(float c[4],
                                        uint32_t a0, uint32_t a1,
                                        uint32_t a2, uint32_t a3,
                                        uint32_t b0, uint32_t b1) {
    asm volatile(
        "mma.sync.aligned.m16n8k16.row.col.f32.f16.f16.f32 "
        "{%0,%1,%2,%3},{%4,%5,%6,%7},{%8,%9},{%0,%1,%2,%3};"
        : "+f"(c[0]), "+f"(c[1]), "+f"(c[2]), "+f"(c[3])
        : "r"(a0), "r"(a1), "r"(a2), "r"(a3), "r"(b0), "r"(b1));
}

// ---------------- FP16 tensor-core GEMM, 3-stage cp.async pipeline ---------
#define BM 128
#define BN 128
#define BKH 32
#define ASTRH 40
#define NSTAGE 3
#define A_STH (BM * ASTRH)
#define B_STH (BN * ASTRH)
#define GSMEM ((NSTAGE * (A_STH + B_STH)) * sizeof(__half))

__device__ __forceinline__ void cp16(uint32_t dst, const void* src) {
    asm volatile("cp.async.cg.shared.global [%0], [%1], 16;"
                 :: "r"(dst), "l"(src));
}
__device__ __forceinline__ void cp_commit() {
    asm volatile("cp.async.commit_group;");
}
template <int N>
__device__ __forceinline__ void cp_wait() {
    asm volatile("cp.async.wait_group %0;" :: "n"(N));
}

template <int EPI>
__global__ void __launch_bounds__(256, 2)
hgemm(const __half* __restrict__ A, const __half* __restrict__ Bt,
      const float* __restrict__ bias, const float* __restrict__ res,
      void* __restrict__ Cv, int M, int N, int K) {
    extern __shared__ __half smem[];
    __half* As = smem;
    __half* Bs = smem + NSTAGE * A_STH;

    int t = threadIdx.x;
    int lane = t & 31, warp = t >> 5;
    int wr = warp >> 2, wc = warp & 3;
    int m0 = blockIdx.y * BM, n0 = blockIdx.x * BN;
    int r16 = lane & 15, s16 = lane >> 4;
    int r8 = lane & 7,  s8 = (lane >> 3) & 1;
    int g8 = lane >> 2, tig = lane & 3;

    float acc[4][4][4];
    #pragma unroll
    for (int i = 0; i < 4; i++)
        #pragma unroll
        for (int j = 0; j < 4; j++)
            #pragma unroll
            for (int e = 0; e < 4; e++) acc[i][j][e] = 0.f;

    const __half* Ag = A + (size_t)m0 * K;
    const __half* Bg = Bt + (size_t)n0 * K;

    auto issue = [&](int kt) {
        int buf = kt % NSTAGE;
        int k0 = kt * BKH;
        uint32_t ab = smem_u32(As + buf * A_STH);
        uint32_t bb = smem_u32(Bs + buf * B_STH);
        #pragma unroll
        for (int r = 0; r < 2; r++) {
            int ia = t + r * 256;
            int row = ia >> 2, c = ia & 3;
            cp16(ab + (row * ASTRH + c * 8) * 2,
                 Ag + (size_t)row * K + k0 + c * 8);
            cp16(bb + (row * ASTRH + c * 8) * 2,
                 Bg + (size_t)row * K + k0 + c * 8);
        }
    };

    int nk = K / BKH;
    issue(0); cp_commit();
    issue(1); cp_commit();

    for (int kt = 0; kt < nk; kt++) {
        cp_wait<1>();
        __syncthreads();
        if (kt + 2 < nk) issue(kt + 2);
        cp_commit();

        int buf = kt % NSTAGE;
        const __half* As_ = As + buf * A_STH;
        const __half* Bs_ = Bs + buf * B_STH;

        #pragma unroll
        for (int ks = 0; ks < 2; ks++) {
            int k0 = ks * 16;
            uint32_t af[4][4], bf[4][2];
            #pragma unroll
            for (int i = 0; i < 4; i++) {
                const __half* p = &As_[(wr * 64 + i * 16 + r16) * ASTRH
                                       + k0 + s16 * 8];
                ldsm_x4(af[i][0], af[i][1], af[i][2], af[i][3], smem_u32(p));
            }
            #pragma unroll
            for (int j = 0; j < 4; j++) {
                const __half* p = &Bs_[(wc * 32 + j * 8 + r8) * ASTRH
                                       + k0 + s8 * 8];
                ldsm_x2(bf[j][0], bf[j][1], smem_u32(p));
            }
            #pragma unroll
            for (int i = 0; i < 4; i++)
                #pragma unroll
                for (int j = 0; j < 4; j++)
                    mma_f16(acc[i][j], af[i][0], af[i][1], af[i][2], af[i][3],
                            bf[j][0], bf[j][1]);
        }
    }

    #pragma unroll
    for (int i = 0; i < 4; i++) {
        int mrow = m0 + wr * 64 + i * 16 + g8;
        #pragma unroll
        for (int j = 0; j < 4; j++) {
            int ncol = n0 + wc * 32 + j * 8 + tig * 2;
            #pragma unroll
            for (int h = 0; h < 2; h++) {
                int mm = mrow + h * 8;
                float vx = acc[i][j][h * 2 + 0] + bias[ncol];
                float vy = acc[i][j][h * 2 + 1] + bias[ncol + 1];
                if (EPI == 1) {
                    const float2 r2 = *(const float2*)(res + (size_t)mm * N + ncol);
                    vx += r2.x; vy += r2.y;
                }
                if (EPI == 2) {
                    vx = vx / (1.f + __expf(-1.702f * vx));
                    vy = vy / (1.f + __expf(-1.702f * vy));
                    __half2 hv = __floats2half2_rn(vx, vy);
                    *(__half2*)((__half*)Cv + (size_t)mm * N + ncol) = hv;
                } else {
                    float2 v; v.x = vx; v.y = vy;
                    *(float2*)((float*)Cv + (size_t)mm * N + ncol) = v;
                }
            }
        }
    }
}

// ---------------- RoPE on q and k (in place on qkv buffer) -----------------
__global__ void rope_kernel(float* __restrict__ qkv,
                            const float* __restrict__ freqs) {
    int n = blockIdx.x;
    int t = threadIdx.x;
    __shared__ float fc[40], fs[40];
    if (t < 40) {
        float f = freqs[(size_t)n * 40 + t];
        fc[t] = cosf(f);
        fs[t] = sinf(f);
    }
    __syncthreads();
    for (int i = t; i < 1280; i += 256) {
        int j = i / 640;
        int rem = i - j * 640;
        int h = rem / 40;
        int d = rem - h * 40;
        float* base = qkv + (size_t)n * (3 * DIM) + j * DIM + h * HD;
        float x1 = base[d];
        float x2 = base[d + 40];
        int plo = d >> 1;
        int phi = 20 + (d >> 1);
        base[d]      = x1 * fc[plo] - x2 * fs[plo];
        base[d + 40] = x2 * fc[phi] + x1 * fs[phi];
    }
}

// ---------------- tensor-core flash attention -------------------------------
// 4 warps, 64 q-rows/CTA (16 per warp), BK=64 keys per tile.
// Qs/Ks: [row][dim] stride 88 halves; Vs: [dim][key] stride 72 halves.
#define FBQ 64
#define FBK 64
#define QKS 88
#define VSS 72

__global__ void __launch_bounds__(128)
flash_tc(const float* __restrict__ qkv, const int* __restrict__ cu,
         __half* __restrict__ out) {
    __shared__ __half Qs[FBQ * QKS];
    __shared__ __half Ks[FBK * QKS];
    __shared__ __half Vs[HD * VSS];
    __shared__ int sstart[FBQ], send[FBQ], sbound[2];

    int q0 = blockIdx.x * FBQ;
    int h = blockIdx.y;
    int t = threadIdx.x;
    int warp = t >> 5, lane = t & 31;
    int r16 = lane & 15, s16 = lane >> 4;
    int r8 = lane & 7, s8 = (lane >> 3) & 1;
    int g8 = lane >> 2, tig = lane & 3;
    const float scale = 0.1118033988749895f;  // 1/sqrt(80)

    // stage Q (scaled) as fp16: 64 rows x 80 dims, 20 float4 per row
    for (int i = t; i < FBQ * 20; i += 128) {
        int r = i / 20, c = (i % 20) * 4;
        float4 qv = *(const float4*)(qkv + (size_t)(q0 + r) * (3 * DIM)
                                     + h * HD + c);
        __half2* dst = (__half2*)&Qs[r * QKS + c];
        dst[0] = __floats2half2_rn(qv.x * scale, qv.y * scale);
        dst[1] = __floats2half2_rn(qv.z * scale, qv.w * scale);
    }
    if (t < FBQ) {
        int row = q0 + t;
        int s = 0, e = SEQ;
        #pragma unroll
        for (int i = 0; i < 4; i++)
            if (row >= cu[i] && row < cu[i + 1]) { s = cu[i]; e = cu[i + 1]; }
        sstart[t] = s; send[t] = e;
    }
    __syncthreads();
    if (t == 0) {
        int mn = sstart[0], mx = send[0];
        for (int i = 1; i < FBQ; i++) {
            mn = min(mn, sstart[i]);
            mx = max(mx, send[i]);
        }
        sbound[0] = mn; sbound[1] = mx;
    }
    __syncthreads();
    int kmin = sbound[0], kmax = sbound[1];

    // per-thread rows (within warp tile of 16)
    int row0 = warp * 16 + g8;       // rows g8 and g8+8
    int st0 = sstart[row0], en0 = send[row0];
    int st1 = sstart[row0 + 8], en1 = send[row0 + 8];

    // hoisted Q A-fragments: 5 k-chunks of 16
    uint32_t qa[5][4];
    #pragma unroll
    for (int ks = 0; ks < 5; ks++) {
        const __half* p = &Qs[(warp * 16 + r16) * QKS + ks * 16 + s16 * 8];
        ldsm_x4(qa[ks][0], qa[ks][1], qa[ks][2], qa[ks][3], smem_u32(p));
    }

    float oacc[10][4];
    #pragma unroll
    for (int f = 0; f < 10; f++)
        #pragma unroll
        for (int e = 0; e < 4; e++) oacc[f][e] = 0.f;
    float m0v = -1e30f, m1v = -1e30f, l0 = 0.f, l1 = 0.f;

    for (int kb = kmin; kb < kmax; kb += FBK) {
        // stage K [key][dim] and V transposed [dim][key]
        for (int i = t; i < FBK * 20; i += 128) {
            int r = i / 20, c = (i % 20) * 4;
            size_t base = (size_t)(kb + r) * (3 * DIM) + h * HD + c;
            float4 kv = *(const float4*)(qkv + base + DIM);
            float4 vv = *(const float4*)(qkv + base + 2 * DIM);
            __half2* kdst = (__half2*)&Ks[r * QKS + c];
            kdst[0] = __floats2half2_rn(kv.x, kv.y);
            kdst[1] = __floats2half2_rn(kv.z, kv.w);
            Vs[(c + 0) * VSS + r] = __float2half_rn(vv.x);
            Vs[(c + 1) * VSS + r] = __float2half_rn(vv.y);
            Vs[(c + 2) * VSS + r] = __float2half_rn(vv.z);
            Vs[(c + 3) * VSS + r] = __float2half_rn(vv.w);
        }
        __syncthreads();

        // S = Q K^T : 8 n-frags x 4 floats
        float sf[8][4];
        #pragma unroll
        for (int j = 0; j < 8; j++)
            #pragma unroll
            for (int e = 0; e < 4; e++) sf[j][e] = 0.f;
        #pragma unroll
        for (int ks = 0; ks < 5; ks++) {
            #pragma unroll
            for (int j = 0; j < 8; j++) {
                uint32_t b0, b1;
                const __half* p = &Ks[(j * 8 + r8) * QKS + ks * 16 + s8 * 8];
                ldsm_x2(b0, b1, smem_u32(p));
                mma_f16(sf[j], qa[ks][0], qa[ks][1], qa[ks][2], qa[ks][3],
                        b0, b1);
            }
        }

        // mask + row max
        float mx0 = -1e30f, mx1 = -1e30f;
        #pragma unroll
        for (int j = 0; j < 8; j++) {
            int c0 = kb + j * 8 + tig * 2, c1 = c0 + 1;
            sf[j][0] = (c0 >= st0 && c0 < en0) ? sf[j][0] : -1e30f;
            sf[j][1] = (c1 >= st0 && c1 < en0) ? sf[j][1] : -1e30f;
            sf[j][2] = (c0 >= st1 && c0 < en1) ? sf[j][2] : -1e30f;
            sf[j][3] = (c1 >= st1 && c1 < en1) ? sf[j][3] : -1e30f;
            mx0 = fmaxf(mx0, fmaxf(sf[j][0], sf[j][1]));
            mx1 = fmaxf(mx1, fmaxf(sf[j][2], sf[j][3]));
        }
        mx0 = fmaxf(mx0, __shfl_xor_sync(~0u, mx0, 1));
        mx0 = fmaxf(mx0, __shfl_xor_sync(~0u, mx0, 2));
        mx1 = fmaxf(mx1, __shfl_xor_sync(~0u, mx1, 1));
        mx1 = fmaxf(mx1, __shfl_xor_sync(~0u, mx1, 2));
        float nm0 = fmaxf(fmaxf(m0v, mx0), -1e28f);
        float nm1 = fmaxf(fmaxf(m1v, mx1), -1e28f);

        // exp, row sums, pack P into A-fragments
        float ps0 = 0.f, ps1 = 0.f;
        uint32_t pa[4][4];   // 4 k16-chunks (64 keys)
        #pragma unroll
        for (int jj = 0; jj < 4; jj++) {
            float p00 = __expf(sf[2 * jj][0] - nm0);
            float p01 = __expf(sf[2 * jj][1] - nm0);
            float p02 = __expf(sf[2 * jj][2] - nm1);
            float p03 = __expf(sf[2 * jj][3] - nm1);
            float p10 = __expf(sf[2 * jj + 1][0] - nm0);
            float p11 = __expf(sf[2 * jj + 1][1] - nm0);
            float p12 = __expf(sf[2 * jj + 1][2] - nm1);
            float p13 = __expf(sf[2 * jj + 1][3] - nm1);
            ps0 += p00 + p01 + p10 + p11;
            ps1 += p02 + p03 + p12 + p13;
            pa[jj][0] = h2_u32(__floats2half2_rn(p00, p01));
            pa[jj][1] = h2_u32(__floats2half2_rn(p02, p03));
            pa[jj][2] = h2_u32(__floats2half2_rn(p10, p11));
            pa[jj][3] = h2_u32(__floats2half2_rn(p12, p13));
        }
        ps0 += __shfl_xor_sync(~0u, ps0, 1);
        ps0 += __shfl_xor_sync(~0u, ps0, 2);
        ps1 += __shfl_xor_sync(~0u, ps1, 1);
        ps1 += __shfl_xor_sync(~0u, ps1, 2);

        float cr0 = __expf(m0v - nm0), cr1 = __expf(m1v - nm1);
        l0 = l0 * cr0 + ps0; l1 = l1 * cr1 + ps1;
        m0v = nm0; m1v = nm1;
        #pragma unroll
        for (int f = 0; f < 10; f++) {
            oacc[f][0] *= cr0; oacc[f][1] *= cr0;
            oacc[f][2] *= cr1; oacc[f][3] *= cr1;
        }

        // O += P V : 10 n-frags (80 dims) x 4 k-chunks
        #pragma unroll
        for (int jj = 0; jj < 4; jj++) {
            #pragma unroll
            for (int f = 0; f < 10; f++) {
                uint32_t b0, b1;
                const __half* p = &Vs[(f * 8 + r8) * VSS + jj * 16 + s8 * 8];
                ldsm_x2(b0, b1, smem_u32(p));
                mma_f16(oacc[f], pa[jj][0], pa[jj][1], pa[jj][2], pa[jj][3],
                        b0, b1);
            }
        }
        __syncthreads();
    }

    float il0 = 1.f / l0, il1 = 1.f / l1;
    __half* o0 = out + (size_t)(q0 + row0) * DIM + h * HD;
    __half* o1 = out + (size_t)(q0 + row0 + 8) * DIM + h * HD;
    #pragma unroll
    for (int f = 0; f < 10; f++) {
        int c = f * 8 + tig * 2;
        *(__half2*)(o0 + c) = __floats2half2_rn(oacc[f][0] * il0,
                                                oacc[f][1] * il0);
        *(__half2*)(o1 + c) = __floats2half2_rn(oacc[f][2] * il1,
                                                oacc[f][3] * il1);
    }
}

// ---------------- launch ---------------------------------------------------
extern "C" void kernel_launch(void* const* d_in, const int* in_sizes, int n_in,
                              void* d_out, int out_size) {
    const float* hidden = (const float*)d_in[0];
    const float* rot    = (const float*)d_in[1];
    const int*   cu     = (const int*)d_in[2];
    const float* w_qkv  = (const float*)d_in[3];
    const float* b_qkv  = (const float*)d_in[4];
    const float* w_proj = (const float*)d_in[5];
    const float* b_proj = (const float*)d_in[6];
    const float* w_fc1  = (const float*)d_in[7];
    const float* b_fc1  = (const float*)d_in[8];
    const float* w_fc2  = (const float*)d_in[9];
    const float* b_fc2  = (const float*)d_in[10];
    const float* ln1s   = (const float*)d_in[11];
    const float* ln1b   = (const float*)d_in[12];
    const float* ln2s   = (const float*)d_in[13];
    const float* ln2b   = (const float*)d_in[14];
    float* out = (float*)d_out;

    __half *lnh, *attnh, *fc1h, *wh;
    float *qkvb, *h1;
    cudaGetSymbolAddress((void**)&lnh, g_lnh);
    cudaGetSymbolAddress((void**)&qkvb, g_qkv);
    cudaGetSymbolAddress((void**)&attnh, g_attnh);
    cudaGetSymbolAddress((void**)&h1, g_h1);
    cudaGetSymbolAddress((void**)&fc1h, g_fc1h);
    cudaGetSymbolAddress((void**)&wh, g_wh);

    cudaFuncSetAttribute(hgemm<0>,
                         cudaFuncAttributeMaxDynamicSharedMemorySize, GSMEM);
    cudaFuncSetAttribute(hgemm<1>,
                         cudaFuncAttributeMaxDynamicSharedMemorySize, GSMEM);
    cudaFuncSetAttribute(hgemm<2>,
                         cudaFuncAttributeMaxDynamicSharedMemorySize, GSMEM);

    // 0. transpose + fp16-convert weights -> [N][K]
    twk<<<dim3(3840 / 32, 1280 / 32), dim3(32, 8)>>>(w_qkv,  wh + W_QKV_OFF,  1280, 3840);
    twk<<<dim3(1280 / 32, 1280 / 32), dim3(32, 8)>>>(w_proj, wh + W_PROJ_OFF, 1280, 1280);
    twk<<<dim3(5120 / 32, 1280 / 32), dim3(32, 8)>>>(w_fc1,  wh + W_FC1_OFF,  1280, 5120);
    twk<<<dim3(1280 / 32, 5120 / 32), dim3(32, 8)>>>(w_fc2,  wh + W_FC2_OFF,  5120, 1280);

    // 1. LN1 -> fp16
    ln_kernel<<<SEQ, 256>>>(hidden, ln1s, ln1b, lnh);
    // 2. QKV GEMM (+bias) -> fp32
    hgemm<0><<<dim3((3 * DIM) / BN, SEQ / BM), 256, GSMEM>>>(
        lnh, wh + W_QKV_OFF, b_qkv, nullptr, qkvb, SEQ, 3 * DIM, DIM);
    // 3. RoPE on q,k
    rope_kernel<<<SEQ, 256>>>(qkvb, rot);
    // 4. tensor-core flash attention -> fp16
    flash_tc<<<dim3(SEQ / FBQ, NHEAD), 128>>>(qkvb, cu, attnh);
    // 5. proj GEMM + bias + residual(hidden) -> h1 fp32
    hgemm<1><<<dim3(DIM / BN, SEQ / BM), 256, GSMEM>>>(
        attnh, wh + W_PROJ_OFF, b_proj, hidden, h1, SEQ, DIM, DIM);
    // 6. LN2 -> fp16
    ln_kernel<<<SEQ, 256>>>(h1, ln2s, ln2b, lnh);
    // 7. FC1 + bias + quickgelu -> fp16
    hgemm<2><<<dim3(HIDDEN / BN, SEQ / BM), 256, GSMEM>>>(
        lnh, wh + W_FC1_OFF, b_fc1, nullptr, fc1h, SEQ, HIDDEN, DIM);
    // 8. FC2 + bias + residual(h1) -> out fp32
    hgemm<1><<<dim3(DIM / BN, SEQ / BM), 256, GSMEM>>>(
        fc1h, wh + W_FC2_OFF, b_fc2, h1, out, SEQ, DIM, HIDDEN);
}

// round 15
// speedup vs baseline: 3.2293x; 1.1412x over previous
#include <cuda_runtime.h>
#include <cuda_fp16.h>
#include <math.h>
#include <stdint.h>

#define SEQ 4096
#define DIM 1280
#define NHEAD 16
#define HD 80
#define HIDDEN 5120

// ---------------- scratch (device globals; no allocation allowed) ----------
__device__ __half g_lnh[SEQ * DIM];
__device__ __half g_qkvh[SEQ * 3 * DIM];
__device__ __half g_attnh[SEQ * DIM];
__device__ float  g_h1[SEQ * DIM];
__device__ __half g_fc1h[SEQ * HIDDEN];
// transposed fp16 weights [N][K]: qkv | proj | fc1 | fc2
#define W_QKV_OFF  0
#define W_PROJ_OFF 4915200
#define W_FC1_OFF  6553600
#define W_FC2_OFF  13107200
__device__ __half g_wh[19660800];

__device__ __forceinline__ uint32_t smem_u32(const void* p) {
    return (uint32_t)__cvta_generic_to_shared(p);
}

__device__ __forceinline__ uint32_t h2_u32(__half2 v) {
    uint32_t u;
    memcpy(&u, &v, 4);
    return u;
}

// ---------------- weight transpose + fp16 convert (once per launch) --------
__global__ void twk(const float* __restrict__ s, __half* __restrict__ d,
                    int K, int N) {
    __shared__ float tile[32][33];
    int c0 = blockIdx.x * 32, r0 = blockIdx.y * 32;
    int tx = threadIdx.x, ty = threadIdx.y;
    #pragma unroll
    for (int i = 0; i < 4; i++)
        tile[ty + 8 * i][tx] = s[(size_t)(r0 + ty + 8 * i) * N + c0 + tx];
    __syncthreads();
    #pragma unroll
    for (int i = 0; i < 4; i++)
        d[(size_t)(c0 + ty + 8 * i) * K + r0 + tx] =
            __float2half_rn(tile[tx][ty + 8 * i]);
}

// ---------------- layernorm (fp32 in, fp16 out) ----------------------------
__global__ void ln_kernel(const float* __restrict__ x,
                          const float* __restrict__ sc,
                          const float* __restrict__ bi,
                          __half* __restrict__ y) {
    int row = blockIdx.x;
    int t = threadIdx.x;
    const float* xr = x + (size_t)row * DIM;
    float s = 0.f, s2 = 0.f;
    #pragma unroll
    for (int i = t; i < DIM; i += 256) {
        float v = xr[i];
        s += v; s2 += v * v;
    }
    #pragma unroll
    for (int o = 16; o; o >>= 1) {
        s  += __shfl_xor_sync(~0u, s,  o);
        s2 += __shfl_xor_sync(~0u, s2, o);
    }
    __shared__ float sh[16];
    int wid = t >> 5, lane = t & 31;
    if (lane == 0) { sh[wid] = s; sh[wid + 8] = s2; }
    __syncthreads();
    float S = 0.f, S2 = 0.f;
    #pragma unroll
    for (int w = 0; w < 8; w++) { S += sh[w]; S2 += sh[w + 8]; }
    float mu = S * (1.f / DIM);
    float var = S2 * (1.f / DIM) - mu * mu;
    float inv = rsqrtf(var + 1e-6f);
    __half* yr = y + (size_t)row * DIM;
    #pragma unroll
    for (int i = t; i < DIM; i += 256)
        yr[i] = __float2half_rn((xr[i] - mu) * inv * sc[i] + bi[i]);
}

// ---------------- shared mma helpers ---------------------------------------
__device__ __forceinline__ void ldsm_x4(uint32_t& r0, uint32_t& r1,
                                        uint32_t& r2, uint32_t& r3,
                                        uint32_t addr) {
    asm volatile("ldmatrix.sync.aligned.m8n8.x4.shared.b16 {%0,%1,%2,%3},[%4];"
                 : "=r"(r0), "=r"(r1), "=r"(r2), "=r"(r3) : "r"(addr));
}
__device__ __forceinline__ void ldsm_x2(uint32_t& r0, uint32_t& r1,
                                        uint32_t addr) {
    asm volatile("ldmatrix.sync.aligned.m8n8.x2.shared.b16 {%0,%1},[%2];"
                 : "=r"(r0), "=r"(r1) : "r"(addr));
}
__device__ __forceinline__ void ldsm_x2_t(uint32_t& r0, uint32_t& r1,
                                          uint32_t addr) {
    asm volatile("ldmatrix.sync.aligned.m8n8.x2.trans.shared.b16 {%0,%1},[%2];"
                 : "=r"(r0), "=r"(r1) : "r"(addr));
}
__device__ __forceinline__ void mma_f16(float c[4],
                                        uint32_t a0, uint32_t a1,
                                        uint32_t a2, uint32_t a3,
                                        uint32_t b0, uint32_t b1) {
    asm volatile(
        "mma.sync.aligned.m16n8k16.row.col.f32.f16.f16.f32 "
        "{%0,%1,%2,%3},{%4,%5,%6,%7},{%8,%9},{%0,%1,%2,%3};"
        : "+f"(c[0]), "+f"(c[1]), "+f"(c[2]), "+f"(c[3])
        : "r"(a0), "r"(a1), "r"(a2), "r"(a3), "r"(b0), "r"(b1));
}

// ---------------- FP16 tensor-core GEMM, 3-stage cp.async pipeline ---------
// EPI 0: fp32 +bias; 1: fp32 +bias+res; 2: fp16 gelu(bias); 3: fp16 +bias
#define BM 128
#define BN 128
#define BKH 32
#define ASTRH 40
#define NSTAGE 3
#define A_STH (BM * ASTRH)
#define B_STH (BN * ASTRH)
#define GSMEM ((NSTAGE * (A_STH + B_STH)) * sizeof(__half))

__device__ __forceinline__ void cp16(uint32_t dst, const void* src) {
    asm volatile("cp.async.cg.shared.global [%0], [%1], 16;"
                 :: "r"(dst), "l"(src));
}
__device__ __forceinline__ void cp_commit() {
    asm volatile("cp.async.commit_group;");
}
template <int N>
__device__ __forceinline__ void cp_wait() {
    asm volatile("cp.async.wait_group %0;" :: "n"(N));
}

template <int EPI>
__global__ void __launch_bounds__(256, 2)
hgemm(const __half* __restrict__ A, const __half* __restrict__ Bt,
      const float* __restrict__ bias, const float* __restrict__ res,
      void* __restrict__ Cv, int M, int N, int K) {
    extern __shared__ __half smem[];
    __half* As = smem;
    __half* Bs = smem + NSTAGE * A_STH;

    int t = threadIdx.x;
    int lane = t & 31, warp = t >> 5;
    int wr = warp >> 2, wc = warp & 3;
    int m0 = blockIdx.y * BM, n0 = blockIdx.x * BN;
    int r16 = lane & 15, s16 = lane >> 4;
    int r8 = lane & 7,  s8 = (lane >> 3) & 1;
    int g8 = lane >> 2, tig = lane & 3;

    float acc[4][4][4];
    #pragma unroll
    for (int i = 0; i < 4; i++)
        #pragma unroll
        for (int j = 0; j < 4; j++)
            #pragma unroll
            for (int e = 0; e < 4; e++) acc[i][j][e] = 0.f;

    const __half* Ag = A + (size_t)m0 * K;
    const __half* Bg = Bt + (size_t)n0 * K;

    auto issue = [&](int kt) {
        int buf = kt % NSTAGE;
        int k0 = kt * BKH;
        uint32_t ab = smem_u32(As + buf * A_STH);
        uint32_t bb = smem_u32(Bs + buf * B_STH);
        #pragma unroll
        for (int r = 0; r < 2; r++) {
            int ia = t + r * 256;
            int row = ia >> 2, c = ia & 3;
            cp16(ab + (row * ASTRH + c * 8) * 2,
                 Ag + (size_t)row * K + k0 + c * 8);
            cp16(bb + (row * ASTRH + c * 8) * 2,
                 Bg + (size_t)row * K + k0 + c * 8);
        }
    };

    int nk = K / BKH;
    issue(0); cp_commit();
    issue(1); cp_commit();

    for (int kt = 0; kt < nk; kt++) {
        cp_wait<1>();
        __syncthreads();
        if (kt + 2 < nk) issue(kt + 2);
        cp_commit();

        int buf = kt % NSTAGE;
        const __half* As_ = As + buf * A_STH;
        const __half* Bs_ = Bs + buf * B_STH;

        #pragma unroll
        for (int ks = 0; ks < 2; ks++) {
            int k0 = ks * 16;
            uint32_t af[4][4], bf[4][2];
            #pragma unroll
            for (int i = 0; i < 4; i++) {
                const __half* p = &As_[(wr * 64 + i * 16 + r16) * ASTRH
                                       + k0 + s16 * 8];
                ldsm_x4(af[i][0], af[i][1], af[i][2], af[i][3], smem_u32(p));
            }
            #pragma unroll
            for (int j = 0; j < 4; j++) {
                const __half* p = &Bs_[(wc * 32 + j * 8 + r8) * ASTRH
                                       + k0 + s8 * 8];
                ldsm_x2(bf[j][0], bf[j][1], smem_u32(p));
            }
            #pragma unroll
            for (int i = 0; i < 4; i++)
                #pragma unroll
                for (int j = 0; j < 4; j++)
                    mma_f16(acc[i][j], af[i][0], af[i][1], af[i][2], af[i][3],
                            bf[j][0], bf[j][1]);
        }
    }

    #pragma unroll
    for (int i = 0; i < 4; i++) {
        int mrow = m0 + wr * 64 + i * 16 + g8;
        #pragma unroll
        for (int j = 0; j < 4; j++) {
            int ncol = n0 + wc * 32 + j * 8 + tig * 2;
            #pragma unroll
            for (int h = 0; h < 2; h++) {
                int mm = mrow + h * 8;
                float vx = acc[i][j][h * 2 + 0] + bias[ncol];
                float vy = acc[i][j][h * 2 + 1] + bias[ncol + 1];
                if (EPI == 1) {
                    const float2 r2 = *(const float2*)(res + (size_t)mm * N + ncol);
                    vx += r2.x; vy += r2.y;
                }
                if (EPI == 2 || EPI == 3) {
                    if (EPI == 2) {
                        vx = vx / (1.f + __expf(-1.702f * vx));
                        vy = vy / (1.f + __expf(-1.702f * vy));
                    }
                    *(__half2*)((__half*)Cv + (size_t)mm * N + ncol) =
                        __floats2half2_rn(vx, vy);
                } else {
                    float2 v; v.x = vx; v.y = vy;
                    *(float2*)((float*)Cv + (size_t)mm * N + ncol) = v;
                }
            }
        }
    }
}

// ---------------- RoPE on fp16 q,k (in place) -------------------------------
__global__ void rope_h(__half* __restrict__ qkv,
                       const float* __restrict__ freqs) {
    int n = blockIdx.x;
    int t = threadIdx.x;    // 128
    __shared__ float fc[40], fs[40];
    if (t < 40) {
        float f = freqs[(size_t)n * 40 + t];
        fc[t] = cosf(f);
        fs[t] = sinf(f);
    }
    __syncthreads();
    for (int i = t; i < 640; i += 128) {
        int j = i / 320;
        int rem = i - j * 320;
        int h = rem / 20;
        int p = rem - h * 20;     // even dim d = 2p
        __half2* base = (__half2*)(qkv + (size_t)n * (3 * DIM) + j * DIM
                                   + h * HD);
        float2 a = __half22float2(base[p]);
        float2 b = __half22float2(base[p + 20]);
        float c1 = fc[p], s1 = fs[p], c2 = fc[20 + p], s2 = fs[20 + p];
        base[p]      = __floats2half2_rn(a.x * c1 - b.x * s1,
                                         a.y * c1 - b.y * s1);
        base[p + 20] = __floats2half2_rn(b.x * c2 + a.x * s2,
                                         b.y * c2 + a.y * s2);
    }
}

// ---------------- tensor-core flash attention -------------------------------
// fp16 qkv input; Q + double-buffered K/V via cp.async; V consumed with
// ldmatrix.trans (no transpose staging). 4 warps, 64 q/CTA, 64 k/tile.
#define FBQ 64
#define FBK 64
#define FST 88
#define FQ_H (FBQ * FST)                 // 5632 halves
#define FSMEM ((FQ_H * 5) * sizeof(__half))  // Q + 2*(K+V) = 56320 B

__global__ void __launch_bounds__(128)
flash_tc(const __half* __restrict__ qkv, const int* __restrict__ cu,
         __half* __restrict__ out) {
    extern __shared__ __half fsm[];
    __half* Qs = fsm;
    __shared__ int sstart[FBQ], send[FBQ], sbound[2];

    int q0 = blockIdx.x * FBQ;
    int h = blockIdx.y;
    int t = threadIdx.x;
    int warp = t >> 5, lane = t & 31;
    int r16 = lane & 15, s16 = lane >> 4;
    int r8 = lane & 7, s8 = (lane >> 3) & 1;
    int g8 = lane >> 2, tig = lane & 3;
    int l16 = lane & 15;
    const float scale = 0.1118033988749895f;  // 1/sqrt(80)

    // issue Q staging (10 x 16B chunks per row)
    for (int i = t; i < FBQ * 10; i += 128) {
        int r = i / 10, c = i - r * 10;
        cp16(smem_u32(Qs + r * FST + c * 8),
             qkv + (size_t)(q0 + r) * (3 * DIM) + h * HD + c * 8);
    }

    if (t < FBQ) {
        int row = q0 + t;
        int s = 0, e = SEQ;
        #pragma unroll
        for (int i = 0; i < 4; i++)
            if (row >= cu[i] && row < cu[i + 1]) { s = cu[i]; e = cu[i + 1]; }
        sstart[t] = s; send[t] = e;
    }
    __syncthreads();
    if (t == 0) {
        int mn = sstart[0], mx = send[0];
        for (int i = 1; i < FBQ; i++) {
            mn = min(mn, sstart[i]);
            mx = max(mx, send[i]);
        }
        sbound[0] = mn; sbound[1] = mx;
    }
    __syncthreads();
    int kmin = sbound[0], kmax = sbound[1];

    auto issueKV = [&](int kb, int buf) {
        __half* Ks_ = fsm + FQ_H + buf * 2 * FQ_H;
        __half* Vs_ = Ks_ + FQ_H;
        for (int i = t; i < FBK * 10; i += 128) {
            int r = i / 10, c = i - r * 10;
            int rr = min(kb + r, SEQ - 1);
            const __half* src = qkv + (size_t)rr * (3 * DIM) + DIM + h * HD
                                + c * 8;
            cp16(smem_u32(Ks_ + r * FST + c * 8), src);
            cp16(smem_u32(Vs_ + r * FST + c * 8), src + DIM);
        }
    };

    issueKV(kmin, 0);
    cp_commit();
    cp_wait<0>();
    __syncthreads();

    int row0 = warp * 16 + g8;
    int st0 = sstart[row0], en0 = send[row0];
    int st1 = sstart[row0 + 8], en1 = send[row0 + 8];

    // hoisted Q A-fragments
    uint32_t qa[5][4];
    #pragma unroll
    for (int ks = 0; ks < 5; ks++) {
        const __half* p = &Qs[(warp * 16 + r16) * FST + ks * 16 + s16 * 8];
        ldsm_x4(qa[ks][0], qa[ks][1], qa[ks][2], qa[ks][3], smem_u32(p));
    }

    float oacc[10][4];
    #pragma unroll
    for (int f = 0; f < 10; f++)
        #pragma unroll
        for (int e = 0; e < 4; e++) oacc[f][e] = 0.f;
    float m0v = -1e30f, m1v = -1e30f, l0 = 0.f, l1 = 0.f;

    int nt = (kmax - kmin + FBK - 1) / FBK;
    for (int idx = 0; idx < nt; idx++) {
        int kb = kmin + idx * FBK;
        if (idx > 0) { cp_wait<0>(); __syncthreads(); }
        if (idx + 1 < nt) { issueKV(kb + FBK, (idx + 1) & 1); cp_commit(); }

        const __half* Ks_ = fsm + FQ_H + (idx & 1) * 2 * FQ_H;
        const __half* Vs_ = Ks_ + FQ_H;

        // S = Q K^T
        float sf[8][4];
        #pragma unroll
        for (int j = 0; j < 8; j++)
            #pragma unroll
            for (int e = 0; e < 4; e++) sf[j][e] = 0.f;
        #pragma unroll
        for (int ks = 0; ks < 5; ks++) {
            #pragma unroll
            for (int j = 0; j < 8; j++) {
                uint32_t b0, b1;
                const __half* p = &Ks_[(j * 8 + r8) * FST + ks * 16 + s8 * 8];
                ldsm_x2(b0, b1, smem_u32(p));
                mma_f16(sf[j], qa[ks][0], qa[ks][1], qa[ks][2], qa[ks][3],
                        b0, b1);
            }
        }

        // scale + mask + row max
        float mx0 = -1e30f, mx1 = -1e30f;
        #pragma unroll
        for (int j = 0; j < 8; j++) {
            int c0 = kb + j * 8 + tig * 2, c1 = c0 + 1;
            sf[j][0] = (c0 >= st0 && c0 < en0) ? sf[j][0] * scale : -1e30f;
            sf[j][1] = (c1 >= st0 && c1 < en0) ? sf[j][1] * scale : -1e30f;
            sf[j][2] = (c0 >= st1 && c0 < en1) ? sf[j][2] * scale : -1e30f;
            sf[j][3] = (c1 >= st1 && c1 < en1) ? sf[j][3] * scale : -1e30f;
            mx0 = fmaxf(mx0, fmaxf(sf[j][0], sf[j][1]));
            mx1 = fmaxf(mx1, fmaxf(sf[j][2], sf[j][3]));
        }
        mx0 = fmaxf(mx0, __shfl_xor_sync(~0u, mx0, 1));
        mx0 = fmaxf(mx0, __shfl_xor_sync(~0u, mx0, 2));
        mx1 = fmaxf(mx1, __shfl_xor_sync(~0u, mx1, 1));
        mx1 = fmaxf(mx1, __shfl_xor_sync(~0u, mx1, 2));
        float nm0 = fmaxf(fmaxf(m0v, mx0), -1e28f);
        float nm1 = fmaxf(fmaxf(m1v, mx1), -1e28f);

        // exp, row sums, pack P into A-fragments
        float ps0 = 0.f, ps1 = 0.f;
        uint32_t pa[4][4];
        #pragma unroll
        for (int jj = 0; jj < 4; jj++) {
            float p00 = __expf(sf[2 * jj][0] - nm0);
            float p01 = __expf(sf[2 * jj][1] - nm0);
            float p02 = __expf(sf[2 * jj][2] - nm1);
            float p03 = __expf(sf[2 * jj][3] - nm1);
            float p10 = __expf(sf[2 * jj + 1][0] - nm0);
            float p11 = __expf(sf[2 * jj + 1][1] - nm0);
            float p12 = __expf(sf[2 * jj + 1][2] - nm1);
            float p13 = __expf(sf[2 * jj + 1][3] - nm1);
            ps0 += p00 + p01 + p10 + p11;
            ps1 += p02 + p03 + p12 + p13;
            pa[jj][0] = h2_u32(__floats2half2_rn(p00, p01));
            pa[jj][1] = h2_u32(__floats2half2_rn(p02, p03));
            pa[jj][2] = h2_u32(__floats2half2_rn(p10, p11));
            pa[jj][3] = h2_u32(__floats2half2_rn(p12, p13));
        }
        ps0 += __shfl_xor_sync(~0u, ps0, 1);
        ps0 += __shfl_xor_sync(~0u, ps0, 2);
        ps1 += __shfl_xor_sync(~0u, ps1, 1);
        ps1 += __shfl_xor_sync(~0u, ps1, 2);

        float cr0 = __expf(m0v - nm0), cr1 = __expf(m1v - nm1);
        l0 = l0 * cr0 + ps0; l1 = l1 * cr1 + ps1;
        m0v = nm0; m1v = nm1;
        #pragma unroll
        for (int f = 0; f < 10; f++) {
            oacc[f][0] *= cr0; oacc[f][1] *= cr0;
            oacc[f][2] *= cr1; oacc[f][3] *= cr1;
        }

        // O += P V via trans-ldmatrix on V[key][dim]
        #pragma unroll
        for (int jj = 0; jj < 4; jj++) {
            #pragma unroll
            for (int f = 0; f < 10; f++) {
                uint32_t b0, b1;
                const __half* p = &Vs_[(jj * 16 + l16) * FST + f * 8];
                ldsm_x2_t(b0, b1, smem_u32(p));
                mma_f16(oacc[f], pa[jj][0], pa[jj][1], pa[jj][2], pa[jj][3],
                        b0, b1);
            }
        }
    }

    float il0 = 1.f / l0, il1 = 1.f / l1;
    __half* o0 = out + (size_t)(q0 + row0) * DIM + h * HD;
    __half* o1 = out + (size_t)(q0 + row0 + 8) * DIM + h * HD;
    #pragma unroll
    for (int f = 0; f < 10; f++) {
        int c = f * 8 + tig * 2;
        *(__half2*)(o0 + c) = __floats2half2_rn(oacc[f][0] * il0,
                                                oacc[f][1] * il0);
        *(__half2*)(o1 + c) = __floats2half2_rn(oacc[f][2] * il1,
                                                oacc[f][3] * il1);
    }
}

// ---------------- launch ---------------------------------------------------
extern "C" void kernel_launch(void* const* d_in, const int* in_sizes, int n_in,
                              void* d_out, int out_size) {
    const float* hidden = (const float*)d_in[0];
    const float* rot    = (const float*)d_in[1];
    const int*   cu     = (const int*)d_in[2];
    const float* w_qkv  = (const float*)d_in[3];
    const float* b_qkv  = (const float*)d_in[4];
    const float* w_proj = (const float*)d_in[5];
    const float* b_proj = (const float*)d_in[6];
    const float* w_fc1  = (const float*)d_in[7];
    const float* b_fc1  = (const float*)d_in[8];
    const float* w_fc2  = (const float*)d_in[9];
    const float* b_fc2  = (const float*)d_in[10];
    const float* ln1s   = (const float*)d_in[11];
    const float* ln1b   = (const float*)d_in[12];
    const float* ln2s   = (const float*)d_in[13];
    const float* ln2b   = (const float*)d_in[14];
    float* out = (float*)d_out;

    __half *lnh, *qkvh, *attnh, *fc1h, *wh;
    float *h1;
    cudaGetSymbolAddress((void**)&lnh, g_lnh);
    cudaGetSymbolAddress((void**)&qkvh, g_qkvh);
    cudaGetSymbolAddress((void**)&attnh, g_attnh);
    cudaGetSymbolAddress((void**)&h1, g_h1);
    cudaGetSymbolAddress((void**)&fc1h, g_fc1h);
    cudaGetSymbolAddress((void**)&wh, g_wh);

    cudaFuncSetAttribute(hgemm<1>,
                         cudaFuncAttributeMaxDynamicSharedMemorySize, GSMEM);
    cudaFuncSetAttribute(hgemm<2>,
                         cudaFuncAttributeMaxDynamicSharedMemorySize, GSMEM);
    cudaFuncSetAttribute(hgemm<3>,
                         cudaFuncAttributeMaxDynamicSharedMemorySize, GSMEM);
    cudaFuncSetAttribute(flash_tc,
                         cudaFuncAttributeMaxDynamicSharedMemorySize, FSMEM);

    // 0. transpose + fp16-convert weights -> [N][K]
    twk<<<dim3(3840 / 32, 1280 / 32), dim3(32, 8)>>>(w_qkv,  wh + W_QKV_OFF,  1280, 3840);
    twk<<<dim3(1280 / 32, 1280 / 32), dim3(32, 8)>>>(w_proj, wh + W_PROJ_OFF, 1280, 1280);
    twk<<<dim3(5120 / 32, 1280 / 32), dim3(32, 8)>>>(w_fc1,  wh + W_FC1_OFF,  1280, 5120);
    twk<<<dim3(1280 / 32, 5120 / 32), dim3(32, 8)>>>(w_fc2,  wh + W_FC2_OFF,  5120, 1280);

    // 1. LN1 -> fp16
    ln_kernel<<<SEQ, 256>>>(hidden, ln1s, ln1b, lnh);
    // 2. QKV GEMM (+bias) -> fp16
    hgemm<3><<<dim3((3 * DIM) / BN, SEQ / BM), 256, GSMEM>>>(
        lnh, wh + W_QKV_OFF, b_qkv, nullptr, qkvh, SEQ, 3 * DIM, DIM);
    // 3. RoPE on q,k (fp16)
    rope_h<<<SEQ, 128>>>(qkvh, rot);
    // 4. tensor-core flash attention -> fp16
    flash_tc<<<dim3(SEQ / FBQ, NHEAD), 128, FSMEM>>>(qkvh, cu, attnh);
    // 5. proj GEMM + bias + residual(hidden) -> h1 fp32
    hgemm<1><<<dim3(DIM / BN, SEQ / BM), 256, GSMEM>>>(
        attnh, wh + W_PROJ_OFF, b_proj, hidden, h1, SEQ, DIM, DIM);
    // 6. LN2 -> fp16
    ln_kernel<<<SEQ, 256>>>(h1, ln2s, ln2b, lnh);
    // 7. FC1 + bias + quickgelu -> fp16
    hgemm<2><<<dim3(HIDDEN / BN, SEQ / BM), 256, GSMEM>>>(
        lnh, wh + W_FC1_OFF, b_fc1, nullptr, fc1h, SEQ, HIDDEN, DIM);
    // 8. FC2 + bias + residual(h1) -> out fp32
    hgemm<1><<<dim3(DIM / BN, SEQ / BM), 256, GSMEM>>>(
        fc1h, wh + W_FC2_OFF, b_fc2, h1, out, SEQ, DIM, HIDDEN);
}

// round 16
// speedup vs baseline: 3.3810x; 1.0470x over previous
#include <cuda_runtime.h>
#include <cuda_fp16.h>
#include <math.h>
#include <stdint.h>

#define SEQ 4096
#define DIM 1280
#define NHEAD 16
#define HD 80
#define HIDDEN 5120

// ---------------- scratch (device globals; no allocation allowed) ----------
__device__ __half g_lnh[SEQ * DIM];
__device__ __half g_qkvh[SEQ * 3 * DIM];
__device__ __half g_attnh[SEQ * DIM];
__device__ float  g_h1[SEQ * DIM];
__device__ __half g_fc1h[SEQ * HIDDEN];
// transposed fp16 weights [N][K]: qkv | proj | fc1 | fc2
#define W_QKV_OFF  0
#define W_PROJ_OFF 4915200
#define W_FC1_OFF  6553600
#define W_FC2_OFF  13107200
__device__ __half g_wh[19660800];

__device__ __forceinline__ uint32_t smem_u32(const void* p) {
    return (uint32_t)__cvta_generic_to_shared(p);
}

__device__ __forceinline__ uint32_t h2_u32(__half2 v) {
    uint32_t u;
    memcpy(&u, &v, 4);
    return u;
}

// ---------------- weight transpose + fp16 convert (once per launch) --------
__global__ void twk(const float* __restrict__ s, __half* __restrict__ d,
                    int K, int N) {
    __shared__ float tile[32][33];
    int c0 = blockIdx.x * 32, r0 = blockIdx.y * 32;
    int tx = threadIdx.x, ty = threadIdx.y;
    #pragma unroll
    for (int i = 0; i < 4; i++)
        tile[ty + 8 * i][tx] = s[(size_t)(r0 + ty + 8 * i) * N + c0 + tx];
    __syncthreads();
    #pragma unroll
    for (int i = 0; i < 4; i++)
        d[(size_t)(c0 + ty + 8 * i) * K + r0 + tx] =
            __float2half_rn(tile[tx][ty + 8 * i]);
}

// ---------------- layernorm (fp32 in, fp16 out), vectorized ----------------
__global__ void ln_kernel(const float* __restrict__ x,
                          const float* __restrict__ sc,
                          const float* __restrict__ bi,
                          __half* __restrict__ y) {
    int row = blockIdx.x;
    int t = threadIdx.x;    // 320 threads, 1 float4 each
    const float4* xr = (const float4*)(x + (size_t)row * DIM);
    float4 v = xr[t];
    float s = v.x + v.y + v.z + v.w;
    float s2 = v.x * v.x + v.y * v.y + v.z * v.z + v.w * v.w;
    #pragma unroll
    for (int o = 16; o; o >>= 1) {
        s  += __shfl_xor_sync(~0u, s,  o);
        s2 += __shfl_xor_sync(~0u, s2, o);
    }
    __shared__ float sh[20];
    int wid = t >> 5, lane = t & 31;
    if (lane == 0) { sh[wid] = s; sh[wid + 10] = s2; }
    __syncthreads();
    float S = 0.f, S2 = 0.f;
    #pragma unroll
    for (int w = 0; w < 10; w++) { S += sh[w]; S2 += sh[w + 10]; }
    float mu = S * (1.f / DIM);
    float var = S2 * (1.f / DIM) - mu * mu;
    float inv = rsqrtf(var + 1e-6f);
    float4 scv = ((const float4*)sc)[t];
    float4 biv = ((const float4*)bi)[t];
    __half2 h0 = __floats2half2_rn((v.x - mu) * inv * scv.x + biv.x,
                                   (v.y - mu) * inv * scv.y + biv.y);
    __half2 h1 = __floats2half2_rn((v.z - mu) * inv * scv.z + biv.z,
                                   (v.w - mu) * inv * scv.w + biv.w);
    __half2* yr = (__half2*)(y + (size_t)row * DIM);
    yr[2 * t] = h0;
    yr[2 * t + 1] = h1;
}

// ---------------- shared mma helpers ---------------------------------------
__device__ __forceinline__ void ldsm_x4(uint32_t& r0, uint32_t& r1,
                                        uint32_t& r2, uint32_t& r3,
                                        uint32_t addr) {
    asm volatile("ldmatrix.sync.aligned.m8n8.x4.shared.b16 {%0,%1,%2,%3},[%4];"
                 : "=r"(r0), "=r"(r1), "=r"(r2), "=r"(r3) : "r"(addr));
}
__device__ __forceinline__ void ldsm_x2(uint32_t& r0, uint32_t& r1,
                                        uint32_t addr) {
    asm volatile("ldmatrix.sync.aligned.m8n8.x2.shared.b16 {%0,%1},[%2];"
                 : "=r"(r0), "=r"(r1) : "r"(addr));
}
__device__ __forceinline__ void ldsm_x2_t(uint32_t& r0, uint32_t& r1,
                                          uint32_t addr) {
    asm volatile("ldmatrix.sync.aligned.m8n8.x2.trans.shared.b16 {%0,%1},[%2];"
                 : "=r"(r0), "=r"(r1) : "r"(addr));
}
__device__ __forceinline__ void mma_f16(float c[4],
                                        uint32_t a0, uint32_t a1,
                                        uint32_t a2, uint32_t a3,
                                        uint32_t b0, uint32_t b1) {
    asm volatile(
        "mma.sync.aligned.m16n8k16.row.col.f32.f16.f16.f32 "
        "{%0,%1,%2,%3},{%4,%5,%6,%7},{%8,%9},{%0,%1,%2,%3};"
        : "+f"(c[0]), "+f"(c[1]), "+f"(c[2]), "+f"(c[3])
        : "r"(a0), "r"(a1), "r"(a2), "r"(a3), "r"(b0), "r"(b1));
}

// ---------------- FP16 tensor-core GEMM, BK=64, 2-stage cp.async -----------
// EPI 0: fp32 +bias; 1: fp32 +bias+res; 2: fp16 gelu(bias); 3: fp16 +bias
#define BM 128
#define BN 128
#define BKH 64
#define ASTRH 72     // 144B row stride: each ldmatrix phase covers 32 banks
#define NSTAGE 2
#define A_STH (BM * ASTRH)
#define B_STH (BN * ASTRH)
#define GSMEM ((NSTAGE * (A_STH + B_STH)) * sizeof(__half))   // 73728 B

__device__ __forceinline__ void cp16(uint32_t dst, const void* src) {
    asm volatile("cp.async.cg.shared.global [%0], [%1], 16;"
                 :: "r"(dst), "l"(src));
}
__device__ __forceinline__ void cp_commit() {
    asm volatile("cp.async.commit_group;");
}
template <int N>
__device__ __forceinline__ void cp_wait() {
    asm volatile("cp.async.wait_group %0;" :: "n"(N));
}

template <int EPI>
__global__ void __launch_bounds__(256, 2)
hgemm(const __half* __restrict__ A, const __half* __restrict__ Bt,
      const float* __restrict__ bias, const float* __restrict__ res,
      void* __restrict__ Cv, int M, int N, int K) {
    extern __shared__ __half smem[];
    __half* As = smem;
    __half* Bs = smem + NSTAGE * A_STH;

    int t = threadIdx.x;
    int lane = t & 31, warp = t >> 5;
    int wr = warp >> 2, wc = warp & 3;
    int m0 = blockIdx.y * BM, n0 = blockIdx.x * BN;
    int r16 = lane & 15, s16 = lane >> 4;
    int g8 = lane >> 2, tig = lane & 3;

    float acc[4][4][4];
    #pragma unroll
    for (int i = 0; i < 4; i++)
        #pragma unroll
        for (int j = 0; j < 4; j++)
            #pragma unroll
            for (int e = 0; e < 4; e++) acc[i][j][e] = 0.f;

    const __half* Ag = A + (size_t)m0 * K;
    const __half* Bg = Bt + (size_t)n0 * K;

    // per stage: A 1024 16B-chunks + B 1024; 256 threads x (4+4)
    auto issue = [&](int kt) {
        int buf = kt & 1;
        int k0 = kt * BKH;
        uint32_t ab = smem_u32(As + buf * A_STH);
        uint32_t bb = smem_u32(Bs + buf * B_STH);
        #pragma unroll
        for (int r = 0; r < 4; r++) {
            int ia = t + r * 256;
            int row = ia >> 3, c = ia & 7;
            cp16(ab + (row * ASTRH + c * 8) * 2,
                 Ag + (size_t)row * K + k0 + c * 8);
            cp16(bb + (row * ASTRH + c * 8) * 2,
                 Bg + (size_t)row * K + k0 + c * 8);
        }
    };

    int nk = K / BKH;
    issue(0); cp_commit();

    for (int kt = 0; kt < nk; kt++) {
        cp_wait<0>();
        __syncthreads();   // stage kt visible; all warps done with buf kt-1
        if (kt + 1 < nk) { issue(kt + 1); cp_commit(); }

        const __half* As_ = As + (kt & 1) * A_STH;
        const __half* Bs_ = Bs + (kt & 1) * B_STH;

        #pragma unroll
        for (int ks = 0; ks < 4; ks++) {
            int k0 = ks * 16;
            uint32_t af[4][4], bf[4][2];
            #pragma unroll
            for (int i = 0; i < 4; i++) {
                const __half* p = &As_[(wr * 64 + i * 16 + r16) * ASTRH
                                       + k0 + s16 * 8];
                ldsm_x4(af[i][0], af[i][1], af[i][2], af[i][3], smem_u32(p));
            }
            // B: 2 x ldsm_x4 -> 4 n-frags (mat order: n-lo/k-lo, n-hi/k-lo,
            // n-lo/k-hi, n-hi/k-hi)
            #pragma unroll
            for (int jj = 0; jj < 2; jj++) {
                uint32_t m0r, m1r, m2r, m3r;
                const __half* p = &Bs_[(wc * 32 + jj * 16 + r16) * ASTRH
                                       + k0 + s16 * 8];
                ldsm_x4(m0r, m1r, m2r, m3r, smem_u32(p));
                bf[2 * jj][0] = m0r;     bf[2 * jj][1] = m2r;
                bf[2 * jj + 1][0] = m1r; bf[2 * jj + 1][1] = m3r;
            }
            #pragma unroll
            for (int i = 0; i < 4; i++)
                #pragma unroll
                for (int j = 0; j < 4; j++)
                    mma_f16(acc[i][j], af[i][0], af[i][1], af[i][2], af[i][3],
                            bf[j][0], bf[j][1]);
        }
        __syncthreads();   // all warps done reading buf kt before overwrite
    }

    #pragma unroll
    for (int i = 0; i < 4; i++) {
        int mrow = m0 + wr * 64 + i * 16 + g8;
        #pragma unroll
        for (int j = 0; j < 4; j++) {
            int ncol = n0 + wc * 32 + j * 8 + tig * 2;
            #pragma unroll
            for (int h = 0; h < 2; h++) {
                int mm = mrow + h * 8;
                float vx = acc[i][j][h * 2 + 0] + bias[ncol];
                float vy = acc[i][j][h * 2 + 1] + bias[ncol + 1];
                if (EPI == 1) {
                    const float2 r2 = *(const float2*)(res + (size_t)mm * N + ncol);
                    vx += r2.x; vy += r2.y;
                }
                if (EPI == 2 || EPI == 3) {
                    if (EPI == 2) {
                        vx = vx / (1.f + __expf(-1.702f * vx));
                        vy = vy / (1.f + __expf(-1.702f * vy));
                    }
                    *(__half2*)((__half*)Cv + (size_t)mm * N + ncol) =
                        __floats2half2_rn(vx, vy);
                } else {
                    float2 v; v.x = vx; v.y = vy;
                    *(float2*)((float*)Cv + (size_t)mm * N + ncol) = v;
                }
            }
        }
    }
}

// ---------------- RoPE on fp16 q,k (in place) -------------------------------
__global__ void rope_h(__half* __restrict__ qkv,
                       const float* __restrict__ freqs) {
    int n = blockIdx.x;
    int t = threadIdx.x;    // 128
    __shared__ float fc[40], fs[40];
    if (t < 40) {
        float f = freqs[(size_t)n * 40 + t];
        fc[t] = cosf(f);
        fs[t] = sinf(f);
    }
    __syncthreads();
    for (int i = t; i < 640; i += 128) {
        int j = i / 320;
        int rem = i - j * 320;
        int h = rem / 20;
        int p = rem - h * 20;
        __half2* base = (__half2*)(qkv + (size_t)n * (3 * DIM) + j * DIM
                                   + h * HD);
        float2 a = __half22float2(base[p]);
        float2 b = __half22float2(base[p + 20]);
        float c1 = fc[p], s1 = fs[p], c2 = fc[20 + p], s2 = fs[20 + p];
        base[p]      = __floats2half2_rn(a.x * c1 - b.x * s1,
                                         a.y * c1 - b.y * s1);
        base[p + 20] = __floats2half2_rn(b.x * c2 + a.x * s2,
                                         b.y * c2 + a.y * s2);
    }
}

// ---------------- tensor-core flash attention -------------------------------
#define FBQ 64
#define FBK 64
#define FST 88
#define FQ_H (FBQ * FST)
#define FSMEM ((FQ_H * 5) * sizeof(__half))

__global__ void __launch_bounds__(128)
flash_tc(const __half* __restrict__ qkv, const int* __restrict__ cu,
         __half* __restrict__ out) {
    extern __shared__ __half fsm[];
    __half* Qs = fsm;
    __shared__ int sstart[FBQ], send[FBQ], sbound[2];

    int q0 = blockIdx.x * FBQ;
    int h = blockIdx.y;
    int t = threadIdx.x;
    int warp = t >> 5, lane = t & 31;
    int r16 = lane & 15, s16 = lane >> 4;
    int r8 = lane & 7, s8 = (lane >> 3) & 1;
    int g8 = lane >> 2, tig = lane & 3;
    int l16 = lane & 15;
    const float scale = 0.1118033988749895f;

    for (int i = t; i < FBQ * 10; i += 128) {
        int r = i / 10, c = i - r * 10;
        cp16(smem_u32(Qs + r * FST + c * 8),
             qkv + (size_t)(q0 + r) * (3 * DIM) + h * HD + c * 8);
    }

    if (t < FBQ) {
        int row = q0 + t;
        int s = 0, e = SEQ;
        #pragma unroll
        for (int i = 0; i < 4; i++)
            if (row >= cu[i] && row < cu[i + 1]) { s = cu[i]; e = cu[i + 1]; }
        sstart[t] = s; send[t] = e;
    }
    __syncthreads();
    if (t == 0) {
        int mn = sstart[0], mx = send[0];
        for (int i = 1; i < FBQ; i++) {
            mn = min(mn, sstart[i]);
            mx = max(mx, send[i]);
        }
        sbound[0] = mn; sbound[1] = mx;
    }
    __syncthreads();
    int kmin = sbound[0], kmax = sbound[1];

    auto issueKV = [&](int kb, int buf) {
        __half* Ks_ = fsm + FQ_H + buf * 2 * FQ_H;
        __half* Vs_ = Ks_ + FQ_H;
        for (int i = t; i < FBK * 10; i += 128) {
            int r = i / 10, c = i - r * 10;
            int rr = min(kb + r, SEQ - 1);
            const __half* src = qkv + (size_t)rr * (3 * DIM) + DIM + h * HD
                                + c * 8;
            cp16(smem_u32(Ks_ + r * FST + c * 8), src);
            cp16(smem_u32(Vs_ + r * FST + c * 8), src + DIM);
        }
    };

    issueKV(kmin, 0);
    cp_commit();
    cp_wait<0>();
    __syncthreads();

    int row0 = warp * 16 + g8;
    int st0 = sstart[row0], en0 = send[row0];
    int st1 = sstart[row0 + 8], en1 = send[row0 + 8];

    uint32_t qa[5][4];
    #pragma unroll
    for (int ks = 0; ks < 5; ks++) {
        const __half* p = &Qs[(warp * 16 + r16) * FST + ks * 16 + s16 * 8];
        ldsm_x4(qa[ks][0], qa[ks][1], qa[ks][2], qa[ks][3], smem_u32(p));
    }

    float oacc[10][4];
    #pragma unroll
    for (int f = 0; f < 10; f++)
        #pragma unroll
        for (int e = 0; e < 4; e++) oacc[f][e] = 0.f;
    float m0v = -1e30f, m1v = -1e30f, l0 = 0.f, l1 = 0.f;

    int nt = (kmax - kmin + FBK - 1) / FBK;
    for (int idx = 0; idx < nt; idx++) {
        int kb = kmin + idx * FBK;
        if (idx > 0) { cp_wait<0>(); __syncthreads(); }
        if (idx + 1 < nt) { issueKV(kb + FBK, (idx + 1) & 1); cp_commit(); }

        const __half* Ks_ = fsm + FQ_H + (idx & 1) * 2 * FQ_H;
        const __half* Vs_ = Ks_ + FQ_H;

        float sf[8][4];
        #pragma unroll
        for (int j = 0; j < 8; j++)
            #pragma unroll
            for (int e = 0; e < 4; e++) sf[j][e] = 0.f;
        #pragma unroll
        for (int ks = 0; ks < 5; ks++) {
            #pragma unroll
            for (int j = 0; j < 8; j++) {
                uint32_t b0, b1;
                const __half* p = &Ks_[(j * 8 + r8) * FST + ks * 16 + s8 * 8];
                ldsm_x2(b0, b1, smem_u32(p));
                mma_f16(sf[j], qa[ks][0], qa[ks][1], qa[ks][2], qa[ks][3],
                        b0, b1);
            }
        }

        float mx0 = -1e30f, mx1 = -1e30f;
        #pragma unroll
        for (int j = 0; j < 8; j++) {
            int c0 = kb + j * 8 + tig * 2, c1 = c0 + 1;
            sf[j][0] = (c0 >= st0 && c0 < en0) ? sf[j][0] * scale : -1e30f;
            sf[j][1] = (c1 >= st0 && c1 < en0) ? sf[j][1] * scale : -1e30f;
            sf[j][2] = (c0 >= st1 && c0 < en1) ? sf[j][2] * scale : -1e30f;
            sf[j][3] = (c1 >= st1 && c1 < en1) ? sf[j][3] * scale : -1e30f;
            mx0 = fmaxf(mx0, fmaxf(sf[j][0], sf[j][1]));
            mx1 = fmaxf(mx1, fmaxf(sf[j][2], sf[j][3]));
        }
        mx0 = fmaxf(mx0, __shfl_xor_sync(~0u, mx0, 1));
        mx0 = fmaxf(mx0, __shfl_xor_sync(~0u, mx0, 2));
        mx1 = fmaxf(mx1, __shfl_xor_sync(~0u, mx1, 1));
        mx1 = fmaxf(mx1, __shfl_xor_sync(~0u, mx1, 2));
        float nm0 = fmaxf(fmaxf(m0v, mx0), -1e28f);
        float nm1 = fmaxf(fmaxf(m1v, mx1), -1e28f);

        float ps0 = 0.f, ps1 = 0.f;
        uint32_t pa[4][4];
        #pragma unroll
        for (int jj = 0; jj < 4; jj++) {
            float p00 = __expf(sf[2 * jj][0] - nm0);
            float p01 = __expf(sf[2 * jj][1] - nm0);
            float p02 = __expf(sf[2 * jj][2] - nm1);
            float p03 = __expf(sf[2 * jj][3] - nm1);
            float p10 = __expf(sf[2 * jj + 1][0] - nm0);
            float p11 = __expf(sf[2 * jj + 1][1] - nm0);
            float p12 = __expf(sf[2 * jj + 1][2] - nm1);
            float p13 = __expf(sf[2 * jj + 1][3] - nm1);
            ps0 += p00 + p01 + p10 + p11;
            ps1 += p02 + p03 + p12 + p13;
            pa[jj][0] = h2_u32(__floats2half2_rn(p00, p01));
            pa[jj][1] = h2_u32(__floats2half2_rn(p02, p03));
            pa[jj][2] = h2_u32(__floats2half2_rn(p10, p11));
            pa[jj][3] = h2_u32(__floats2half2_rn(p12, p13));
        }
        ps0 += __shfl_xor_sync(~0u, ps0, 1);
        ps0 += __shfl_xor_sync(~0u, ps0, 2);
        ps1 += __shfl_xor_sync(~0u, ps1, 1);
        ps1 += __shfl_xor_sync(~0u, ps1, 2);

        float cr0 = __expf(m0v - nm0), cr1 = __expf(m1v - nm1);
        l0 = l0 * cr0 + ps0; l1 = l1 * cr1 + ps1;
        m0v = nm0; m1v = nm1;
        #pragma unroll
        for (int f = 0; f < 10; f++) {
            oacc[f][0] *= cr0; oacc[f][1] *= cr0;
            oacc[f][2] *= cr1; oacc[f][3] *= cr1;
        }

        #pragma unroll
        for (int jj = 0; jj < 4; jj++) {
            #pragma unroll
            for (int f = 0; f < 10; f++) {
                uint32_t b0, b1;
                const __half* p = &Vs_[(jj * 16 + l16) * FST + f * 8];
                ldsm_x2_t(b0, b1, smem_u32(p));
                mma_f16(oacc[f], pa[jj][0], pa[jj][1], pa[jj][2], pa[jj][3],
                        b0, b1);
            }
        }
    }

    float il0 = 1.f / l0, il1 = 1.f / l1;
    __half* o0 = out + (size_t)(q0 + row0) * DIM + h * HD;
    __half* o1 = out + (size_t)(q0 + row0 + 8) * DIM + h * HD;
    #pragma unroll
    for (int f = 0; f < 10; f++) {
        int c = f * 8 + tig * 2;
        *(__half2*)(o0 + c) = __floats2half2_rn(oacc[f][0] * il0,
                                                oacc[f][1] * il0);
        *(__half2*)(o1 + c) = __floats2half2_rn(oacc[f][2] * il1,
                                                oacc[f][3] * il1);
    }
}

// ---------------- launch ---------------------------------------------------
extern "C" void kernel_launch(void* const* d_in, const int* in_sizes, int n_in,
                              void* d_out, int out_size) {
    const float* hidden = (const float*)d_in[0];
    const float* rot    = (const float*)d_in[1];
    const int*   cu     = (const int*)d_in[2];
    const float* w_qkv  = (const float*)d_in[3];
    const float* b_qkv  = (const float*)d_in[4];
    const float* w_proj = (const float*)d_in[5];
    const float* b_proj = (const float*)d_in[6];
    const float* w_fc1  = (const float*)d_in[7];
    const float* b_fc1  = (const float*)d_in[8];
    const float* w_fc2  = (const float*)d_in[9];
    const float* b_fc2  = (const float*)d_in[10];
    const float* ln1s   = (const float*)d_in[11];
    const float* ln1b   = (const float*)d_in[12];
    const float* ln2s   = (const float*)d_in[13];
    const float* ln2b   = (const float*)d_in[14];
    float* out = (float*)d_out;

    __half *lnh, *qkvh, *attnh, *fc1h, *wh;
    float *h1;
    cudaGetSymbolAddress((void**)&lnh, g_lnh);
    cudaGetSymbolAddress((void**)&qkvh, g_qkvh);
    cudaGetSymbolAddress((void**)&attnh, g_attnh);
    cudaGetSymbolAddress((void**)&h1, g_h1);
    cudaGetSymbolAddress((void**)&fc1h, g_fc1h);
    cudaGetSymbolAddress((void**)&wh, g_wh);

    cudaFuncSetAttribute(hgemm<1>,
                         cudaFuncAttributeMaxDynamicSharedMemorySize, GSMEM);
    cudaFuncSetAttribute(hgemm<2>,
                         cudaFuncAttributeMaxDynamicSharedMemorySize, GSMEM);
    cudaFuncSetAttribute(hgemm<3>,
                         cudaFuncAttributeMaxDynamicSharedMemorySize, GSMEM);
    cudaFuncSetAttribute(flash_tc,
                         cudaFuncAttributeMaxDynamicSharedMemorySize, FSMEM);

    // 0. transpose + fp16-convert weights -> [N][K]
    twk<<<dim3(3840 / 32, 1280 / 32), dim3(32, 8)>>>(w_qkv,  wh + W_QKV_OFF,  1280, 3840);
    twk<<<dim3(1280 / 32, 1280 / 32), dim3(32, 8)>>>(w_proj, wh + W_PROJ_OFF, 1280, 1280);
    twk<<<dim3(5120 / 32, 1280 / 32), dim3(32, 8)>>>(w_fc1,  wh + W_FC1_OFF,  1280, 5120);
    twk<<<dim3(1280 / 32, 5120 / 32), dim3(32, 8)>>>(w_fc2,  wh + W_FC2_OFF,  5120, 1280);

    // 1. LN1 -> fp16
    ln_kernel<<<SEQ, 320>>>(hidden, ln1s, ln1b, lnh);
    // 2. QKV GEMM (+bias) -> fp16
    hgemm<3><<<dim3((3 * DIM) / BN, SEQ / BM), 256, GSMEM>>>(
        lnh, wh + W_QKV_OFF, b_qkv, nullptr, qkvh, SEQ, 3 * DIM, DIM);
    // 3. RoPE on q,k (fp16)
    rope_h<<<SEQ, 128>>>(qkvh, rot);
    // 4. tensor-core flash attention -> fp16
    flash_tc<<<dim3(SEQ / FBQ, NHEAD), 128, FSMEM>>>(qkvh, cu, attnh);
    // 5. proj GEMM + bias + residual(hidden) -> h1 fp32
    hgemm<1><<<dim3(DIM / BN, SEQ / BM), 256, GSMEM>>>(
        attnh, wh + W_PROJ_OFF, b_proj, hidden, h1, SEQ, DIM, DIM);
    // 6. LN2 -> fp16
    ln_kernel<<<SEQ, 320>>>(h1, ln2s, ln2b, lnh);
    // 7. FC1 + bias + quickgelu -> fp16
    hgemm<2><<<dim3(HIDDEN / BN, SEQ / BM), 256, GSMEM>>>(
        lnh, wh + W_FC1_OFF, b_fc1, nullptr, fc1h, SEQ, HIDDEN, DIM);
    // 8. FC2 + bias + residual(h1) -> out fp32
    hgemm<1><<<dim3(DIM / BN, SEQ / BM), 256, GSMEM>>>(
        fc1h, wh + W_FC2_OFF, b_fc2, h1, out, SEQ, DIM, HIDDEN);
}